// round 8
// baseline (speedup 1.0000x reference)
#include <cuda_runtime.h>
#include <cuda_bf16.h>
#include <math.h>
#include <stdint.h>

#define NB 4
#define NC 256
#define NT 4096

typedef __nv_bfloat16 bf16;

__device__ bf16  g_xnhi[NB * NT * NC];
__device__ bf16  g_xnlo[NB * NT * NC];
__device__ bf16  g_qhi [NB * NT * NC];
__device__ bf16  g_qlo [NB * NT * NC];
__device__ bf16  g_khi [NB * NT * NC];
__device__ bf16  g_klo [NB * NT * NC];
__device__ bf16  g_vThi[NC * NB * NT];
__device__ bf16  g_vTlo[NC * NB * NT];
__device__ float g_s   [(size_t)NB * NT * NT];
__device__ bf16  g_ahi [(size_t)NB * NT * NT];
__device__ bf16  g_alo [(size_t)NB * NT * NT];
__device__ float g_o   [NB * NT * NC];
__device__ bf16  g_wqhi[NC * NC], g_wqlo[NC * NC];
__device__ bf16  g_wkhi[NC * NC], g_wklo[NC * NC];
__device__ bf16  g_wvhi[NC * NC], g_wvlo[NC * NC];

__device__ __forceinline__ uint32_t smem_u32(const void* p) {
    uint32_t a;
    asm("{ .reg .u64 t; cvta.to.shared.u64 t, %1; cvt.u32.u64 %0, t; }" : "=r"(a) : "l"(p));
    return a;
}
__device__ __forceinline__ void cp16(uint32_t s, const void* g) {
    asm volatile("cp.async.cg.shared.global [%0], [%1], 16;" :: "r"(s), "l"(g));
}
__device__ __forceinline__ void cp_commit() { asm volatile("cp.async.commit_group;" ::: "memory"); }
template <int N> __device__ __forceinline__ void cp_wait() {
    asm volatile("cp.async.wait_group %0;" :: "n"(N) : "memory");
}
__device__ __forceinline__ void ldm_x4(uint32_t* r, uint32_t addr) {
    asm volatile("ldmatrix.sync.aligned.m8n8.x4.shared.b16 {%0,%1,%2,%3}, [%4];"
                 : "=r"(r[0]), "=r"(r[1]), "=r"(r[2]), "=r"(r[3]) : "r"(addr));
}
__device__ __forceinline__ void mma16816(float* d, const uint32_t* a, const uint32_t* b) {
    asm volatile(
        "mma.sync.aligned.m16n8k16.row.col.f32.bf16.bf16.f32 "
        "{%0,%1,%2,%3}, {%4,%5,%6,%7}, {%8,%9}, {%0,%1,%2,%3};"
        : "+f"(d[0]), "+f"(d[1]), "+f"(d[2]), "+f"(d[3])
        : "r"(a[0]), "r"(a[1]), "r"(a[2]), "r"(a[3]), "r"(b[0]), "r"(b[1]));
}
__device__ __forceinline__ uint32_t swz(uint32_t off) { return off ^ ((off >> 3) & 0x70); }
__device__ __forceinline__ uint32_t pack2b(float a, float b) {
    return (uint32_t)__bfloat16_as_ushort(__float2bfloat16(a))
         | ((uint32_t)__bfloat16_as_ushort(__float2bfloat16(b)) << 16);
}

// ============================================================
// split-bf16 GEMM (3 products): D = Ahi*Bhi^T + Ahi*Blo^T + Alo*Bhi^T
// BM=BN=128, BK=32. 512 thr = 16 warps (4x4), warp tile 32x32.
// 3-stage cp.async pipeline (96 KB smem). EPI=0: fp32. EPI=1: pair.
// ============================================================
template <int EPI>
__global__ void __launch_bounds__(512, 1) mma_gemm(
    const bf16* __restrict__ Ahi, const bf16* __restrict__ Alo, long ldA, long strideA,
    const bf16* __restrict__ Bhi, const bf16* __restrict__ Blo, long ldB, long strideB,
    float* __restrict__ Cf, bf16* __restrict__ Chi, bf16* __restrict__ Clo,
    long ldC, long strideC, int K)
{
    extern __shared__ char dyn[];
    const uint32_t sbase = smem_u32(dyn);
    const int tid = threadIdx.x;
    const int wid = tid >> 5, lane = tid & 31;
    const int warpM = wid & 3, warpN = wid >> 2;

    const int z = blockIdx.z;
    const long m0 = (long)blockIdx.y * 128;
    const long n0 = (long)blockIdx.x * 128;
    const bf16* pAh = Ahi + (size_t)z * strideA + (size_t)m0 * ldA;
    const bf16* pAl = Alo + (size_t)z * strideA + (size_t)m0 * ldA;
    const bf16* pBh = Bhi + (size_t)z * strideB + (size_t)n0 * ldB;
    const bf16* pBl = Blo + (size_t)z * strideB + (size_t)n0 * ldB;

    const int nk = K / 32;
    const uint32_t STAGE = 32768;

    auto load_stage = [&](int st, int ks) {
        uint32_t base = sbase + st * STAGE;
#pragma unroll
        for (int i = 0; i < 2; i++) {
            int cid = tid + i * 512;          // 0..1023
            int m = cid >> 3, c = cid & 7;
            int part = c >> 2, kc = c & 3;
            uint32_t off = swz((uint32_t)(m * 128 + c * 16));
            cp16(base + off,           (part ? pAl : pAh) + (size_t)m * ldA + ks * 32 + kc * 8);
            cp16(base + 16384u + off,  (part ? pBl : pBh) + (size_t)m * ldB + ks * 32 + kc * 8);
        }
    };

    float acc[2][4][4] = {};
    load_stage(0, 0); cp_commit();
    load_stage(1, 1); cp_commit();

    const int lr = lane & 7, lg = lane >> 3;

    for (int ks = 0; ks < nk; ks++) {
        if (ks + 1 < nk) cp_wait<1>(); else cp_wait<0>();
        __syncthreads();
        if (ks + 2 < nk) { load_stage((ks + 2) % 3, ks + 2); cp_commit(); }

        uint32_t aBase = sbase + (uint32_t)(ks % 3) * STAGE;
        uint32_t bBase = aBase + 16384u;

#pragma unroll
        for (int kst = 0; kst < 2; kst++) {
            const uint32_t kb = kst * 32;

            uint32_t ah[2][4];
#pragma unroll
            for (int mf = 0; mf < 2; mf++) {
                uint32_t row = warpM * 32 + mf * 16 + lr + ((lg & 1) << 3);
                ldm_x4(ah[mf], aBase + swz(row * 128 + kb + ((lg >> 1) << 4)));
            }
            uint32_t bh[4][2];
#pragma unroll
            for (int p = 0; p < 2; p++) {
                uint32_t row = warpN * 32 + p * 16 + lr + ((lg >> 1) << 3);
                uint32_t t[4];
                ldm_x4(t, bBase + swz(row * 128 + kb + ((lg & 1) << 4)));
                bh[2*p][0] = t[0]; bh[2*p][1] = t[1];
                bh[2*p+1][0] = t[2]; bh[2*p+1][1] = t[3];
            }
#pragma unroll
            for (int mf = 0; mf < 2; mf++)
#pragma unroll
                for (int nf = 0; nf < 4; nf++)
                    mma16816(acc[mf][nf], ah[mf], bh[nf]);

            uint32_t bl[4][2];
#pragma unroll
            for (int p = 0; p < 2; p++) {
                uint32_t row = warpN * 32 + p * 16 + lr + ((lg >> 1) << 3);
                uint32_t t[4];
                ldm_x4(t, bBase + swz(row * 128 + 64 + kb + ((lg & 1) << 4)));
                bl[2*p][0] = t[0]; bl[2*p][1] = t[1];
                bl[2*p+1][0] = t[2]; bl[2*p+1][1] = t[3];
            }
#pragma unroll
            for (int mf = 0; mf < 2; mf++)
#pragma unroll
                for (int nf = 0; nf < 4; nf++)
                    mma16816(acc[mf][nf], ah[mf], bl[nf]);

#pragma unroll
            for (int mf = 0; mf < 2; mf++) {
                uint32_t al[4];
                uint32_t row = warpM * 32 + mf * 16 + lr + ((lg & 1) << 3);
                ldm_x4(al, aBase + swz(row * 128 + 64 + kb + ((lg >> 1) << 4)));
#pragma unroll
                for (int nf = 0; nf < 4; nf++)
                    mma16816(acc[mf][nf], al, bh[nf]);
            }
        }
    }

    const int qr = lane >> 2, qc = (lane & 3) * 2;
#pragma unroll
    for (int mf = 0; mf < 2; mf++) {
#pragma unroll
        for (int nf = 0; nf < 4; nf++) {
            long r0  = m0 + warpM * 32 + mf * 16 + qr;
            long col = n0 + warpN * 32 + nf * 8 + qc;
            if (EPI == 0) {
                float* d0 = Cf + (size_t)z * strideC + (size_t)r0 * ldC + col;
                *(float2*)d0             = make_float2(acc[mf][nf][0], acc[mf][nf][1]);
                *(float2*)(d0 + 8 * ldC) = make_float2(acc[mf][nf][2], acc[mf][nf][3]);
            } else {
#pragma unroll
                for (int h = 0; h < 2; h++) {
                    float v0 = acc[mf][nf][2*h], v1 = acc[mf][nf][2*h+1];
                    float h0 = __bfloat162float(__float2bfloat16(v0));
                    float h1 = __bfloat162float(__float2bfloat16(v1));
                    size_t idx = (size_t)z * strideC + (size_t)(r0 + h * 8) * ldC + col;
                    *(uint32_t*)(Chi + idx) = pack2b(v0, v1);
                    *(uint32_t*)(Clo + idx) = pack2b(v0 - h0, v1 - h1);
                }
            }
        }
    }
}

// ============================================================
__global__ void __launch_bounds__(256) ln_kernel(
    const float* __restrict__ x, const float* __restrict__ gamma,
    const float* __restrict__ beta, bf16* __restrict__ xnhi, bf16* __restrict__ xnlo)
{
    __shared__ float sx[32][NC + 1];
    __shared__ float psum[8][33], psq[8][33];
    __shared__ float smu[32], srs[32];
    int b = blockIdx.y, n0 = blockIdx.x * 32;
    const float* xb = x + (size_t)b * NC * NT;

    for (int i = threadIdx.x; i < NC * 32; i += 256) {
        int c = i >> 5, t = i & 31;
        sx[t][c] = xb[(size_t)c * NT + n0 + t];
    }
    __syncthreads();
    int t = threadIdx.x & 31, g = threadIdx.x >> 5;
    float s0 = 0.f, s1 = 0.f;
#pragma unroll
    for (int j = 0; j < 32; j++) { float v = sx[t][g * 32 + j]; s0 += v; s1 += v * v; }
    psum[g][t] = s0; psq[g][t] = s1;
    __syncthreads();
    if (threadIdx.x < 32) {
        float a = 0.f, bb = 0.f;
#pragma unroll
        for (int j = 0; j < 8; j++) { a += psum[j][threadIdx.x]; bb += psq[j][threadIdx.x]; }
        float mu = a * (1.0f / NC);
        smu[threadIdx.x] = mu;
        srs[threadIdx.x] = rsqrtf(bb * (1.0f / NC) - mu * mu + 1e-5f);
    }
    __syncthreads();
    size_t base = ((size_t)b * NT + n0) * NC;
    for (int i = threadIdx.x; i < NC * 32; i += 256) {
        int tok = i >> 8, c = i & 255;
        float r = (sx[tok][c] - smu[tok]) * srs[tok] * gamma[c] + beta[c];
        bf16 h = __float2bfloat16(r);
        xnhi[base + (size_t)tok * NC + c] = h;
        xnlo[base + (size_t)tok * NC + c] = __float2bfloat16(r - __bfloat162float(h));
    }
}

__global__ void prep_kernel(
    const float* __restrict__ Wq, const float* __restrict__ Wk, const float* __restrict__ Wv,
    bf16* qh, bf16* ql, bf16* kh, bf16* kl, bf16* vh, bf16* vl)
{
    int n = blockIdx.x, k = threadIdx.x;
    size_t src = (size_t)k * NC + n, dst = (size_t)n * NC + k;
    float v; bf16 h;
    v = Wq[src]; h = __float2bfloat16(v); qh[dst] = h; ql[dst] = __float2bfloat16(v - __bfloat162float(h));
    v = Wk[src]; h = __float2bfloat16(v); kh[dst] = h; kl[dst] = __float2bfloat16(v - __bfloat162float(h));
    v = Wv[src]; h = __float2bfloat16(v); vh[dst] = h; vl[dst] = __float2bfloat16(v - __bfloat162float(h));
}

__global__ void __launch_bounds__(256) mix_kernel(
    const float* __restrict__ w1, const float* __restrict__ w2,
    const float* __restrict__ S, bf16* __restrict__ ahi, bf16* __restrict__ alo)
{
    size_t ro = ((size_t)blockIdx.y * NT + blockIdx.x) * NT;
    const float4* row4 = (const float4*)(S + ro);
    int tid = threadIdx.x;
    __shared__ float sred[8];

    float4 v[4];
    float mx = -1e30f;
#pragma unroll
    for (int g = 0; g < 4; g++) {
        v[g] = row4[g * 256 + tid];
        mx = fmaxf(mx, fmaxf(fmaxf(v[g].x, v[g].y), fmaxf(v[g].z, v[g].w)));
    }
#pragma unroll
    for (int o = 16; o; o >>= 1) mx = fmaxf(mx, __shfl_xor_sync(0xffffffffu, mx, o));
    if ((tid & 31) == 0) sred[tid >> 5] = mx;
    __syncthreads();
    mx = sred[0];
#pragma unroll
    for (int i = 1; i < 8; i++) mx = fmaxf(mx, sred[i]);
    __syncthreads();

    float4 e[4];
    float sum = 0.f;
#pragma unroll
    for (int g = 0; g < 4; g++) {
        e[g].x = __expf(v[g].x - mx); e[g].y = __expf(v[g].y - mx);
        e[g].z = __expf(v[g].z - mx); e[g].w = __expf(v[g].w - mx);
        sum += e[g].x + e[g].y + e[g].z + e[g].w;
    }
#pragma unroll
    for (int o = 16; o; o >>= 1) sum += __shfl_xor_sync(0xffffffffu, sum, o);
    if ((tid & 31) == 0) sred[tid >> 5] = sum;
    __syncthreads();
    sum = 0.f;
#pragma unroll
    for (int i = 0; i < 8; i++) sum += sred[i];

    float e1 = __expf(w1[0]), e2 = __expf(w2[0]);
    float a1 = e1 / (e1 + e2), a2 = e2 / (e1 + e2);
    float inv = a1 / sum;

    uint2* oh = (uint2*)(ahi + ro);
    uint2* ol = (uint2*)(alo + ro);
#pragma unroll
    for (int g = 0; g < 4; g++) {
        float p0 = e[g].x * inv + a2 * fmaxf(v[g].x, 0.f) * fmaxf(v[g].x, 0.f);
        float p1 = e[g].y * inv + a2 * fmaxf(v[g].y, 0.f) * fmaxf(v[g].y, 0.f);
        float p2 = e[g].z * inv + a2 * fmaxf(v[g].z, 0.f) * fmaxf(v[g].z, 0.f);
        float p3 = e[g].w * inv + a2 * fmaxf(v[g].w, 0.f) * fmaxf(v[g].w, 0.f);
        float h0 = __bfloat162float(__float2bfloat16(p0));
        float h1 = __bfloat162float(__float2bfloat16(p1));
        float h2 = __bfloat162float(__float2bfloat16(p2));
        float h3 = __bfloat162float(__float2bfloat16(p3));
        oh[g * 256 + tid] = make_uint2(pack2b(p0, p1), pack2b(p2, p3));
        ol[g * 256 + tid] = make_uint2(pack2b(p0 - h0, p1 - h1), pack2b(p2 - h2, p3 - h3));
    }
}

__global__ void out_kernel(const float* __restrict__ o, const bf16* __restrict__ xnhi,
                           const bf16* __restrict__ xnlo, float* __restrict__ out)
{
    __shared__ float tile[32][33];
    int b = blockIdx.z, n0 = blockIdx.x * 32, c0 = blockIdx.y * 32;
    for (int r = threadIdx.y; r < 32; r += 8) {
        size_t idx = ((size_t)b * NT + n0 + r) * NC + c0 + threadIdx.x;
        tile[r][threadIdx.x] = o[idx] + __bfloat162float(xnhi[idx]) + __bfloat162float(xnlo[idx]);
    }
    __syncthreads();
    for (int r = threadIdx.y; r < 32; r += 8)
        out[((size_t)b * NC + c0 + r) * NT + n0 + threadIdx.x] = tile[threadIdx.x][r];
}

// ============================================================
extern "C" void kernel_launch(void* const* d_in, const int* in_sizes, int n_in,
                              void* d_out, int out_size)
{
    const float* x     = (const float*)d_in[0];
    const float* gamma = (const float*)d_in[1];
    const float* beta  = (const float*)d_in[2];
    const float* Wq    = (const float*)d_in[3];
    const float* Wk    = (const float*)d_in[4];
    const float* Wv    = (const float*)d_in[5];
    const float* w1    = (const float*)d_in[6];
    const float* w2    = (const float*)d_in[7];
    float* out = (float*)d_out;

    bf16 *xnhi, *xnlo, *qhi, *qlo, *khi, *klo, *vThi, *vTlo;
    bf16 *wqhi, *wqlo, *wkhi, *wklo, *wvhi, *wvlo, *ahi, *alo;
    float *s, *o;
    cudaGetSymbolAddress((void**)&xnhi, g_xnhi); cudaGetSymbolAddress((void**)&xnlo, g_xnlo);
    cudaGetSymbolAddress((void**)&qhi,  g_qhi);  cudaGetSymbolAddress((void**)&qlo,  g_qlo);
    cudaGetSymbolAddress((void**)&khi,  g_khi);  cudaGetSymbolAddress((void**)&klo,  g_klo);
    cudaGetSymbolAddress((void**)&vThi, g_vThi); cudaGetSymbolAddress((void**)&vTlo, g_vTlo);
    cudaGetSymbolAddress((void**)&wqhi, g_wqhi); cudaGetSymbolAddress((void**)&wqlo, g_wqlo);
    cudaGetSymbolAddress((void**)&wkhi, g_wkhi); cudaGetSymbolAddress((void**)&wklo, g_wklo);
    cudaGetSymbolAddress((void**)&wvhi, g_wvhi); cudaGetSymbolAddress((void**)&wvlo, g_wvlo);
    cudaGetSymbolAddress((void**)&ahi,  g_ahi);  cudaGetSymbolAddress((void**)&alo,  g_alo);
    cudaGetSymbolAddress((void**)&s, g_s); cudaGetSymbolAddress((void**)&o, g_o);

    cudaFuncSetAttribute((const void*)mma_gemm<0>, cudaFuncAttributeMaxDynamicSharedMemorySize, 98304);
    cudaFuncSetAttribute((const void*)mma_gemm<1>, cudaFuncAttributeMaxDynamicSharedMemorySize, 98304);

    // 1) LayerNorm -> xn pair
    ln_kernel<<<dim3(NT / 32, NB), 256>>>(x, gamma, beta, xnhi, xnlo);
    // 2) weight transpose+split
    prep_kernel<<<NC, NC>>>(Wq, Wk, Wv, wqhi, wqlo, wkhi, wklo, wvhi, wvlo);
    // 3-5) Q, K, V^T projections
    mma_gemm<1><<<dim3(2, 128, 1), 512, 98304>>>(
        xnhi, xnlo, NC, 0, wqhi, wqlo, NC, 0, nullptr, qhi, qlo, NC, 0, NC);
    mma_gemm<1><<<dim3(2, 128, 1), 512, 98304>>>(
        xnhi, xnlo, NC, 0, wkhi, wklo, NC, 0, nullptr, khi, klo, NC, 0, NC);
    mma_gemm<1><<<dim3(128, 2, 1), 512, 98304>>>(
        wvhi, wvlo, NC, 0, xnhi, xnlo, NC, 0, nullptr, vThi, vTlo, (long)NB * NT, 0, NC);
    // 6) S = Q K^T per batch (fp32)  <- ncu profile target (6th launch)
    mma_gemm<0><<<dim3(32, 32, NB), 512, 98304>>>(
        qhi, qlo, NC, (long)NT * NC, khi, klo, NC, (long)NT * NC,
        s, nullptr, nullptr, NT, (long)NT * NT, NC);
    // 7) attn mix -> pair
    mix_kernel<<<dim3(NT, NB), 256>>>(w1, w2, s, ahi, alo);
    // 8) O = attn @ V per batch
    mma_gemm<0><<<dim3(2, 32, NB), 512, 98304>>>(
        ahi, alo, NT, (long)NT * NT, vThi, vTlo, (long)NB * NT, NT,
        o, nullptr, nullptr, NC, (long)NT * NC, NT);
    // 9) transpose + residual
    out_kernel<<<dim3(NT / 32, NC / 32, NB), dim3(32, 8)>>>(o, xnhi, xnlo, out);
}

// round 9
// speedup vs baseline: 1.5406x; 1.5406x over previous
#include <cuda_runtime.h>
#include <cuda_fp16.h>
#include <math.h>
#include <stdint.h>

#define NB 4
#define NC 256
#define NT 4096

typedef __half h16;

__device__ h16   g_xnhi[NB * NT * NC];
__device__ h16   g_xnlo[NB * NT * NC];
__device__ h16   g_qhi [NB * NT * NC];
__device__ h16   g_qlo [NB * NT * NC];
__device__ h16   g_khi [NB * NT * NC];
__device__ h16   g_klo [NB * NT * NC];
__device__ h16   g_vThi[NC * NB * NT];
__device__ h16   g_vTlo[NC * NB * NT];
__device__ float g_s   [(size_t)NB * NT * NT];
__device__ h16   g_ahi [(size_t)NB * NT * NT];
__device__ float g_o   [NB * NT * NC];
__device__ h16   g_wqhi[NC * NC], g_wqlo[NC * NC];
__device__ h16   g_wkhi[NC * NC], g_wklo[NC * NC];
__device__ h16   g_wvhi[NC * NC], g_wvlo[NC * NC];

__device__ __forceinline__ uint32_t smem_u32(const void* p) {
    uint32_t a;
    asm("{ .reg .u64 t; cvta.to.shared.u64 t, %1; cvt.u32.u64 %0, t; }" : "=r"(a) : "l"(p));
    return a;
}
__device__ __forceinline__ void cp16(uint32_t s, const void* g) {
    asm volatile("cp.async.cg.shared.global [%0], [%1], 16;" :: "r"(s), "l"(g));
}
__device__ __forceinline__ void cp_commit() { asm volatile("cp.async.commit_group;" ::: "memory"); }
template <int N> __device__ __forceinline__ void cp_wait() {
    asm volatile("cp.async.wait_group %0;" :: "n"(N) : "memory");
}
__device__ __forceinline__ void ldm_x4(uint32_t* r, uint32_t addr) {
    asm volatile("ldmatrix.sync.aligned.m8n8.x4.shared.b16 {%0,%1,%2,%3}, [%4];"
                 : "=r"(r[0]), "=r"(r[1]), "=r"(r[2]), "=r"(r[3]) : "r"(addr));
}
__device__ __forceinline__ void mma16816(float* d, const uint32_t* a, const uint32_t* b) {
    asm volatile(
        "mma.sync.aligned.m16n8k16.row.col.f32.f16.f16.f32 "
        "{%0,%1,%2,%3}, {%4,%5,%6,%7}, {%8,%9}, {%0,%1,%2,%3};"
        : "+f"(d[0]), "+f"(d[1]), "+f"(d[2]), "+f"(d[3])
        : "r"(a[0]), "r"(a[1]), "r"(a[2]), "r"(a[3]), "r"(b[0]), "r"(b[1]));
}
__device__ __forceinline__ uint32_t swz(uint32_t off) { return off ^ ((off >> 3) & 0x70); }
__device__ __forceinline__ uint32_t pack2h(float a, float b) {
    return (uint32_t)__half_as_ushort(__float2half_rn(a))
         | ((uint32_t)__half_as_ushort(__float2half_rn(b)) << 16);
}

// ============================================================
// split-fp16 GEMM. NPROD=3: Ahi*Bhi + Ahi*Blo + Alo*Bhi.
// NPROD=2: Ahi*Bhi + Ahi*Blo  (A lo-plane never loaded).
// BM=BN=128, BK=32, 256 thr (8 warps 2x4), warp tile 64x32,
// 2-stage cp.async, 2 CTA/SM. EPI=0: fp32 out. EPI=1: pair out.
// ============================================================
template <int EPI, int NPROD>
__global__ void __launch_bounds__(256, 2) mma_gemm(
    const h16* __restrict__ Ahi, const h16* __restrict__ Alo, long ldA, long strideA,
    const h16* __restrict__ Bhi, const h16* __restrict__ Blo, long ldB, long strideB,
    float* __restrict__ Cf, h16* __restrict__ Chi, h16* __restrict__ Clo,
    long ldC, long strideC, int K)
{
    extern __shared__ char dyn[];
    const uint32_t sbase = smem_u32(dyn);
    const int tid = threadIdx.x;
    const int wid = tid >> 5, lane = tid & 31;
    const int warpM = wid & 1, warpN = wid >> 1;

    const int z = blockIdx.z;
    const long m0 = (long)blockIdx.y * 128;
    const long n0 = (long)blockIdx.x * 128;
    const h16* pAh = Ahi + (size_t)z * strideA + (size_t)m0 * ldA;
    const h16* pAl = (NPROD == 3) ? Alo + (size_t)z * strideA + (size_t)m0 * ldA : nullptr;
    const h16* pBh = Bhi + (size_t)z * strideB + (size_t)n0 * ldB;
    const h16* pBl = Blo + (size_t)z * strideB + (size_t)n0 * ldB;

    const int nk = K / 32;
    const uint32_t STAGE = 32768;

    auto load_stage = [&](int st, int ks) {
        uint32_t base = sbase + st * STAGE;
#pragma unroll
        for (int i = 0; i < 4; i++) {
            int cid = tid + i * 256;
            int m = cid >> 3, c = cid & 7;
            int part = c >> 2, kc = c & 3;
            uint32_t off = swz((uint32_t)(m * 128 + c * 16));
            if (NPROD == 3 || part == 0)
                cp16(base + off, (part ? pAl : pAh) + (size_t)m * ldA + ks * 32 + kc * 8);
            cp16(base + 16384u + off, (part ? pBl : pBh) + (size_t)m * ldB + ks * 32 + kc * 8);
        }
    };

    float acc[4][4][4] = {};
    load_stage(0, 0);
    cp_commit();

    const int lr = lane & 7, lg = lane >> 3;

    for (int ks = 0; ks < nk; ks++) {
        int cur = ks & 1;
        if (ks + 1 < nk) { load_stage(cur ^ 1, ks + 1); cp_commit(); cp_wait<1>(); }
        else             { cp_wait<0>(); }
        __syncthreads();

        uint32_t aBase = sbase + cur * STAGE;
        uint32_t bBase = aBase + 16384u;

#pragma unroll
        for (int kst = 0; kst < 2; kst++) {
            const uint32_t kb = kst * 32;
            uint32_t ah[4][4];
#pragma unroll
            for (int mf = 0; mf < 4; mf++) {
                uint32_t row = warpM * 64 + mf * 16 + lr + ((lg & 1) << 3);
                ldm_x4(ah[mf], aBase + swz(row * 128 + kb + ((lg >> 1) << 4)));
            }
            uint32_t bh[4][2];
#pragma unroll
            for (int p = 0; p < 2; p++) {
                uint32_t row = warpN * 32 + p * 16 + lr + ((lg >> 1) << 3);
                uint32_t t[4];
                ldm_x4(t, bBase + swz(row * 128 + kb + ((lg & 1) << 4)));
                bh[2*p][0] = t[0]; bh[2*p][1] = t[1];
                bh[2*p+1][0] = t[2]; bh[2*p+1][1] = t[3];
            }
#pragma unroll
            for (int mf = 0; mf < 4; mf++)
#pragma unroll
                for (int nf = 0; nf < 4; nf++)
                    mma16816(acc[mf][nf], ah[mf], bh[nf]);

            uint32_t bl[4][2];
#pragma unroll
            for (int p = 0; p < 2; p++) {
                uint32_t row = warpN * 32 + p * 16 + lr + ((lg >> 1) << 3);
                uint32_t t[4];
                ldm_x4(t, bBase + swz(row * 128 + 64 + kb + ((lg & 1) << 4)));
                bl[2*p][0] = t[0]; bl[2*p][1] = t[1];
                bl[2*p+1][0] = t[2]; bl[2*p+1][1] = t[3];
            }
#pragma unroll
            for (int mf = 0; mf < 4; mf++)
#pragma unroll
                for (int nf = 0; nf < 4; nf++)
                    mma16816(acc[mf][nf], ah[mf], bl[nf]);

            if (NPROD == 3) {
#pragma unroll
                for (int mf = 0; mf < 4; mf++) {
                    uint32_t al[4];
                    uint32_t row = warpM * 64 + mf * 16 + lr + ((lg & 1) << 3);
                    ldm_x4(al, aBase + swz(row * 128 + 64 + kb + ((lg >> 1) << 4)));
#pragma unroll
                    for (int nf = 0; nf < 4; nf++)
                        mma16816(acc[mf][nf], al, bh[nf]);
                }
            }
        }
        __syncthreads();
    }

    const int qr = lane >> 2, qc = (lane & 3) * 2;
#pragma unroll
    for (int mf = 0; mf < 4; mf++) {
#pragma unroll
        for (int nf = 0; nf < 4; nf++) {
            long r0  = m0 + warpM * 64 + mf * 16 + qr;
            long col = n0 + warpN * 32 + nf * 8 + qc;
            if (EPI == 0) {
                float* d0 = Cf + (size_t)z * strideC + (size_t)r0 * ldC + col;
                *(float2*)d0             = make_float2(acc[mf][nf][0], acc[mf][nf][1]);
                *(float2*)(d0 + 8 * ldC) = make_float2(acc[mf][nf][2], acc[mf][nf][3]);
            } else {
#pragma unroll
                for (int h = 0; h < 2; h++) {
                    float v0 = acc[mf][nf][2*h], v1 = acc[mf][nf][2*h+1];
                    float h0 = __half2float(__float2half_rn(v0));
                    float h1 = __half2float(__float2half_rn(v1));
                    size_t idx = (size_t)z * strideC + (size_t)(r0 + h * 8) * ldC + col;
                    *(uint32_t*)(Chi + idx) = pack2h(v0, v1);
                    *(uint32_t*)(Clo + idx) = pack2h(v0 - h0, v1 - h1);
                }
            }
        }
    }
}

// ============================================================
__global__ void __launch_bounds__(256) ln_kernel(
    const float* __restrict__ x, const float* __restrict__ gamma,
    const float* __restrict__ beta, h16* __restrict__ xnhi, h16* __restrict__ xnlo)
{
    __shared__ float sx[32][NC + 1];
    __shared__ float psum[8][33], psq[8][33];
    __shared__ float smu[32], srs[32];
    int b = blockIdx.y, n0 = blockIdx.x * 32;
    const float* xb = x + (size_t)b * NC * NT;

    for (int i = threadIdx.x; i < NC * 32; i += 256) {
        int c = i >> 5, t = i & 31;
        sx[t][c] = xb[(size_t)c * NT + n0 + t];
    }
    __syncthreads();
    int t = threadIdx.x & 31, g = threadIdx.x >> 5;
    float s0 = 0.f, s1 = 0.f;
#pragma unroll
    for (int j = 0; j < 32; j++) { float v = sx[t][g * 32 + j]; s0 += v; s1 += v * v; }
    psum[g][t] = s0; psq[g][t] = s1;
    __syncthreads();
    if (threadIdx.x < 32) {
        float a = 0.f, bb = 0.f;
#pragma unroll
        for (int j = 0; j < 8; j++) { a += psum[j][threadIdx.x]; bb += psq[j][threadIdx.x]; }
        float mu = a * (1.0f / NC);
        smu[threadIdx.x] = mu;
        srs[threadIdx.x] = rsqrtf(bb * (1.0f / NC) - mu * mu + 1e-5f);
    }
    __syncthreads();
    size_t base = ((size_t)b * NT + n0) * NC;
    for (int i = threadIdx.x; i < NC * 32; i += 256) {
        int tok = i >> 8, c = i & 255;
        float r = (sx[tok][c] - smu[tok]) * srs[tok] * gamma[c] + beta[c];
        float h = __half2float(__float2half_rn(r));
        xnhi[base + (size_t)tok * NC + c] = __float2half_rn(r);
        xnlo[base + (size_t)tok * NC + c] = __float2half_rn(r - h);
    }
}

__global__ void prep_kernel(
    const float* __restrict__ Wq, const float* __restrict__ Wk, const float* __restrict__ Wv,
    h16* qh, h16* ql, h16* kh, h16* kl, h16* vh, h16* vl)
{
    int n = blockIdx.x, k = threadIdx.x;
    size_t src = (size_t)k * NC + n, dst = (size_t)n * NC + k;
    float v, h;
    v = Wq[src]; h = __half2float(__float2half_rn(v)); qh[dst] = __float2half_rn(v); ql[dst] = __float2half_rn(v - h);
    v = Wk[src]; h = __half2float(__float2half_rn(v)); kh[dst] = __float2half_rn(v); kl[dst] = __float2half_rn(v - h);
    v = Wv[src]; h = __half2float(__float2half_rn(v)); vh[dst] = __float2half_rn(v); vl[dst] = __float2half_rn(v - h);
}

// mix: attn = a1*softmax + a2*relu^2, fp16 hi-only out
__global__ void __launch_bounds__(256) mix_kernel(
    const float* __restrict__ w1, const float* __restrict__ w2,
    const float* __restrict__ S, h16* __restrict__ ahi)
{
    size_t ro = ((size_t)blockIdx.y * NT + blockIdx.x) * NT;
    const float4* row4 = (const float4*)(S + ro);
    int tid = threadIdx.x;
    __shared__ float sred[8];

    float4 v[4];
    float mx = -1e30f;
#pragma unroll
    for (int g = 0; g < 4; g++) {
        v[g] = row4[g * 256 + tid];
        mx = fmaxf(mx, fmaxf(fmaxf(v[g].x, v[g].y), fmaxf(v[g].z, v[g].w)));
    }
#pragma unroll
    for (int o = 16; o; o >>= 1) mx = fmaxf(mx, __shfl_xor_sync(0xffffffffu, mx, o));
    if ((tid & 31) == 0) sred[tid >> 5] = mx;
    __syncthreads();
    mx = sred[0];
#pragma unroll
    for (int i = 1; i < 8; i++) mx = fmaxf(mx, sred[i]);
    __syncthreads();

    float4 e[4];
    float sum = 0.f;
#pragma unroll
    for (int g = 0; g < 4; g++) {
        e[g].x = __expf(v[g].x - mx); e[g].y = __expf(v[g].y - mx);
        e[g].z = __expf(v[g].z - mx); e[g].w = __expf(v[g].w - mx);
        sum += e[g].x + e[g].y + e[g].z + e[g].w;
    }
#pragma unroll
    for (int o = 16; o; o >>= 1) sum += __shfl_xor_sync(0xffffffffu, sum, o);
    if ((tid & 31) == 0) sred[tid >> 5] = sum;
    __syncthreads();
    sum = 0.f;
#pragma unroll
    for (int i = 0; i < 8; i++) sum += sred[i];

    float e1 = __expf(w1[0]), e2 = __expf(w2[0]);
    float a1 = e1 / (e1 + e2), a2 = e2 / (e1 + e2);
    float inv = a1 / sum;

    uint2* oh = (uint2*)(ahi + ro);
#pragma unroll
    for (int g = 0; g < 4; g++) {
        float p0 = e[g].x * inv + a2 * fmaxf(v[g].x, 0.f) * fmaxf(v[g].x, 0.f);
        float p1 = e[g].y * inv + a2 * fmaxf(v[g].y, 0.f) * fmaxf(v[g].y, 0.f);
        float p2 = e[g].z * inv + a2 * fmaxf(v[g].z, 0.f) * fmaxf(v[g].z, 0.f);
        float p3 = e[g].w * inv + a2 * fmaxf(v[g].w, 0.f) * fmaxf(v[g].w, 0.f);
        oh[g * 256 + tid] = make_uint2(pack2h(p0, p1), pack2h(p2, p3));
    }
}

__global__ void out_kernel(const float* __restrict__ o, const h16* __restrict__ xnhi,
                           const h16* __restrict__ xnlo, float* __restrict__ out)
{
    __shared__ float tile[32][33];
    int b = blockIdx.z, n0 = blockIdx.x * 32, c0 = blockIdx.y * 32;
    for (int r = threadIdx.y; r < 32; r += 8) {
        size_t idx = ((size_t)b * NT + n0 + r) * NC + c0 + threadIdx.x;
        tile[r][threadIdx.x] = o[idx] + __half2float(xnhi[idx]) + __half2float(xnlo[idx]);
    }
    __syncthreads();
    for (int r = threadIdx.y; r < 32; r += 8)
        out[((size_t)b * NC + c0 + r) * NT + n0 + threadIdx.x] = tile[threadIdx.x][r];
}

// ============================================================
extern "C" void kernel_launch(void* const* d_in, const int* in_sizes, int n_in,
                              void* d_out, int out_size)
{
    const float* x     = (const float*)d_in[0];
    const float* gamma = (const float*)d_in[1];
    const float* beta  = (const float*)d_in[2];
    const float* Wq    = (const float*)d_in[3];
    const float* Wk    = (const float*)d_in[4];
    const float* Wv    = (const float*)d_in[5];
    const float* w1    = (const float*)d_in[6];
    const float* w2    = (const float*)d_in[7];
    float* out = (float*)d_out;

    h16 *xnhi, *xnlo, *qhi, *qlo, *khi, *klo, *vThi, *vTlo;
    h16 *wqhi, *wqlo, *wkhi, *wklo, *wvhi, *wvlo, *ahi;
    float *s, *o;
    cudaGetSymbolAddress((void**)&xnhi, g_xnhi); cudaGetSymbolAddress((void**)&xnlo, g_xnlo);
    cudaGetSymbolAddress((void**)&qhi,  g_qhi);  cudaGetSymbolAddress((void**)&qlo,  g_qlo);
    cudaGetSymbolAddress((void**)&khi,  g_khi);  cudaGetSymbolAddress((void**)&klo,  g_klo);
    cudaGetSymbolAddress((void**)&vThi, g_vThi); cudaGetSymbolAddress((void**)&vTlo, g_vTlo);
    cudaGetSymbolAddress((void**)&wqhi, g_wqhi); cudaGetSymbolAddress((void**)&wqlo, g_wqlo);
    cudaGetSymbolAddress((void**)&wkhi, g_wkhi); cudaGetSymbolAddress((void**)&wklo, g_wklo);
    cudaGetSymbolAddress((void**)&wvhi, g_wvhi); cudaGetSymbolAddress((void**)&wvlo, g_wvlo);
    cudaGetSymbolAddress((void**)&ahi,  g_ahi);
    cudaGetSymbolAddress((void**)&s, g_s); cudaGetSymbolAddress((void**)&o, g_o);

    cudaFuncSetAttribute((const void*)mma_gemm<1,3>, cudaFuncAttributeMaxDynamicSharedMemorySize, 65536);
    cudaFuncSetAttribute((const void*)mma_gemm<0,2>, cudaFuncAttributeMaxDynamicSharedMemorySize, 65536);

    // 1) LayerNorm -> xn pair
    ln_kernel<<<dim3(NT / 32, NB), 256>>>(x, gamma, beta, xnhi, xnlo);
    // 2) weight transpose+split
    prep_kernel<<<NC, NC>>>(Wq, Wk, Wv, wqhi, wqlo, wkhi, wklo, wvhi, wvlo);
    // 3-5) Q, K, V^T projections (3-product, pair out)
    mma_gemm<1,3><<<dim3(2, 128, 1), 256, 65536>>>(
        xnhi, xnlo, NC, 0, wqhi, wqlo, NC, 0, nullptr, qhi, qlo, NC, 0, NC);
    mma_gemm<1,3><<<dim3(2, 128, 1), 256, 65536>>>(
        xnhi, xnlo, NC, 0, wkhi, wklo, NC, 0, nullptr, khi, klo, NC, 0, NC);
    mma_gemm<1,3><<<dim3(128, 2, 1), 256, 65536>>>(
        wvhi, wvlo, NC, 0, xnhi, xnlo, NC, 0, nullptr, vThi, vTlo, (long)NB * NT, 0, NC);
    // 6) S = Q K^T (2-product: qhi x k-pair)  <- ncu 6th launch
    mma_gemm<0,2><<<dim3(32, 32, NB), 256, 65536>>>(
        qhi, nullptr, NC, (long)NT * NC, khi, klo, NC, (long)NT * NC,
        s, nullptr, nullptr, NT, (long)NT * NT, NC);
    // 7) attn mix -> fp16 hi only
    mix_kernel<<<dim3(NT, NB), 256>>>(w1, w2, s, ahi);
    // 8) O = attn @ V (2-product: ahi x vT-pair)
    mma_gemm<0,2><<<dim3(2, 32, NB), 256, 65536>>>(
        ahi, nullptr, NT, (long)NT * NT, vThi, vTlo, (long)NB * NT, NT,
        o, nullptr, nullptr, NC, (long)NT * NC, NT);
    // 9) transpose + residual
    out_kernel<<<dim3(NT / 32, NC / 32, NB), dim3(32, 8)>>>(o, xnhi, xnlo, out);
}

// round 10
// speedup vs baseline: 2.1009x; 1.3637x over previous
#include <cuda_runtime.h>
#include <cuda_fp16.h>
#include <math.h>
#include <stdint.h>

#define NB 4
#define NC 256
#define NT 4096

typedef __half h16;

__device__ h16   g_xnhi[NB * NT * NC];
__device__ h16   g_xnlo[NB * NT * NC];
__device__ h16   g_qhi [NB * NT * NC];
__device__ h16   g_qlo [NB * NT * NC];
__device__ h16   g_khi [NB * NT * NC];
__device__ h16   g_klo [NB * NT * NC];
__device__ h16   g_vThi[NC * NB * NT];
__device__ h16   g_vTlo[NC * NB * NT];
__device__ float g_s   [(size_t)NB * NT * NT];
__device__ h16   g_ahi [(size_t)NB * NT * NT];
__device__ float g_o   [NB * NT * NC];
__device__ h16   g_wqhi[NC * NC], g_wqlo[NC * NC];
__device__ h16   g_wkhi[NC * NC], g_wklo[NC * NC];
__device__ h16   g_wvhi[NC * NC], g_wvlo[NC * NC];

__device__ __forceinline__ uint32_t smem_u32(const void* p) {
    uint32_t a;
    asm("{ .reg .u64 t; cvta.to.shared.u64 t, %1; cvt.u32.u64 %0, t; }" : "=r"(a) : "l"(p));
    return a;
}
__device__ __forceinline__ void cp16(uint32_t s, const void* g) {
    asm volatile("cp.async.cg.shared.global [%0], [%1], 16;" :: "r"(s), "l"(g));
}
__device__ __forceinline__ void cp_commit() { asm volatile("cp.async.commit_group;" ::: "memory"); }
template <int N> __device__ __forceinline__ void cp_wait() {
    asm volatile("cp.async.wait_group %0;" :: "n"(N) : "memory");
}
__device__ __forceinline__ void ldm_x4(uint32_t* r, uint32_t addr) {
    asm volatile("ldmatrix.sync.aligned.m8n8.x4.shared.b16 {%0,%1,%2,%3}, [%4];"
                 : "=r"(r[0]), "=r"(r[1]), "=r"(r[2]), "=r"(r[3]) : "r"(addr));
}
__device__ __forceinline__ void mma16816(float* d, const uint32_t* a, const uint32_t* b) {
    asm volatile(
        "mma.sync.aligned.m16n8k16.row.col.f32.f16.f16.f32 "
        "{%0,%1,%2,%3}, {%4,%5,%6,%7}, {%8,%9}, {%0,%1,%2,%3};"
        : "+f"(d[0]), "+f"(d[1]), "+f"(d[2]), "+f"(d[3])
        : "r"(a[0]), "r"(a[1]), "r"(a[2]), "r"(a[3]), "r"(b[0]), "r"(b[1]));
}
__device__ __forceinline__ uint32_t swz(uint32_t off) { return off ^ ((off >> 3) & 0x70); }
__device__ __forceinline__ uint32_t pack2h(float a, float b) {
    return (uint32_t)__half_as_ushort(__float2half_rn(a))
         | ((uint32_t)__half_as_ushort(__float2half_rn(b)) << 16);
}

// ============================================================
// split-fp16 GEMM.
//   NPROD=3: Ahi*Bhi + Ahi*Blo + Alo*Bhi   (A,B pairs)
//   NPROD=2: Ahi*Bhi + Ahi*Blo             (A hi only)
//   NPROD=1: Ahi*Bhi                       (pure fp16)
// BM=BN=128, BK=32, 256 thr (8 warps 2x4), warp tile 64x32,
// 2-stage cp.async, 2 CTA/SM. EPI=0: fp32 out. EPI=1: pair out.
// ============================================================
template <int EPI, int NPROD>
__global__ void __launch_bounds__(256, 2) mma_gemm(
    const h16* __restrict__ Ahi, const h16* __restrict__ Alo, long ldA, long strideA,
    const h16* __restrict__ Bhi, const h16* __restrict__ Blo, long ldB, long strideB,
    float* __restrict__ Cf, h16* __restrict__ Chi, h16* __restrict__ Clo,
    long ldC, long strideC, int K)
{
    extern __shared__ char dyn[];
    const uint32_t sbase = smem_u32(dyn);
    const int tid = threadIdx.x;
    const int wid = tid >> 5, lane = tid & 31;
    const int warpM = wid & 1, warpN = wid >> 1;

    const int z = blockIdx.z;
    const long m0 = (long)blockIdx.y * 128;
    const long n0 = (long)blockIdx.x * 128;
    const h16* pAh = Ahi + (size_t)z * strideA + (size_t)m0 * ldA;
    const h16* pAl = (NPROD == 3) ? Alo + (size_t)z * strideA + (size_t)m0 * ldA : nullptr;
    const h16* pBh = Bhi + (size_t)z * strideB + (size_t)n0 * ldB;
    const h16* pBl = (NPROD >= 2) ? Blo + (size_t)z * strideB + (size_t)n0 * ldB : nullptr;

    const int nk = K / 32;
    const uint32_t STAGE = 32768;

    auto load_stage = [&](int st, int ks) {
        uint32_t base = sbase + st * STAGE;
#pragma unroll
        for (int i = 0; i < 4; i++) {
            int cid = tid + i * 256;
            int m = cid >> 3, c = cid & 7;
            int part = c >> 2, kc = c & 3;
            uint32_t off = swz((uint32_t)(m * 128 + c * 16));
            if (NPROD == 3 || part == 0)
                cp16(base + off, (part ? pAl : pAh) + (size_t)m * ldA + ks * 32 + kc * 8);
            if (NPROD >= 2 || part == 0)
                cp16(base + 16384u + off, (part ? pBl : pBh) + (size_t)m * ldB + ks * 32 + kc * 8);
        }
    };

    float acc[4][4][4] = {};
    load_stage(0, 0);
    cp_commit();

    const int lr = lane & 7, lg = lane >> 3;

    for (int ks = 0; ks < nk; ks++) {
        int cur = ks & 1;
        if (ks + 1 < nk) { load_stage(cur ^ 1, ks + 1); cp_commit(); cp_wait<1>(); }
        else             { cp_wait<0>(); }
        __syncthreads();

        uint32_t aBase = sbase + cur * STAGE;
        uint32_t bBase = aBase + 16384u;

#pragma unroll
        for (int kst = 0; kst < 2; kst++) {
            const uint32_t kb = kst * 32;
            uint32_t ah[4][4];
#pragma unroll
            for (int mf = 0; mf < 4; mf++) {
                uint32_t row = warpM * 64 + mf * 16 + lr + ((lg & 1) << 3);
                ldm_x4(ah[mf], aBase + swz(row * 128 + kb + ((lg >> 1) << 4)));
            }
            uint32_t bh[4][2];
#pragma unroll
            for (int p = 0; p < 2; p++) {
                uint32_t row = warpN * 32 + p * 16 + lr + ((lg >> 1) << 3);
                uint32_t t[4];
                ldm_x4(t, bBase + swz(row * 128 + kb + ((lg & 1) << 4)));
                bh[2*p][0] = t[0]; bh[2*p][1] = t[1];
                bh[2*p+1][0] = t[2]; bh[2*p+1][1] = t[3];
            }
#pragma unroll
            for (int mf = 0; mf < 4; mf++)
#pragma unroll
                for (int nf = 0; nf < 4; nf++)
                    mma16816(acc[mf][nf], ah[mf], bh[nf]);

            if (NPROD >= 2) {
                uint32_t bl[4][2];
#pragma unroll
                for (int p = 0; p < 2; p++) {
                    uint32_t row = warpN * 32 + p * 16 + lr + ((lg >> 1) << 3);
                    uint32_t t[4];
                    ldm_x4(t, bBase + swz(row * 128 + 64 + kb + ((lg & 1) << 4)));
                    bl[2*p][0] = t[0]; bl[2*p][1] = t[1];
                    bl[2*p+1][0] = t[2]; bl[2*p+1][1] = t[3];
                }
#pragma unroll
                for (int mf = 0; mf < 4; mf++)
#pragma unroll
                    for (int nf = 0; nf < 4; nf++)
                        mma16816(acc[mf][nf], ah[mf], bl[nf]);
            }

            if (NPROD == 3) {
#pragma unroll
                for (int mf = 0; mf < 4; mf++) {
                    uint32_t al[4];
                    uint32_t row = warpM * 64 + mf * 16 + lr + ((lg & 1) << 3);
                    ldm_x4(al, aBase + swz(row * 128 + 64 + kb + ((lg >> 1) << 4)));
#pragma unroll
                    for (int nf = 0; nf < 4; nf++)
                        mma16816(acc[mf][nf], al, bh[nf]);
                }
            }
        }
        __syncthreads();
    }

    const int qr = lane >> 2, qc = (lane & 3) * 2;
#pragma unroll
    for (int mf = 0; mf < 4; mf++) {
#pragma unroll
        for (int nf = 0; nf < 4; nf++) {
            long r0  = m0 + warpM * 64 + mf * 16 + qr;
            long col = n0 + warpN * 32 + nf * 8 + qc;
            if (EPI == 0) {
                float* d0 = Cf + (size_t)z * strideC + (size_t)r0 * ldC + col;
                *(float2*)d0             = make_float2(acc[mf][nf][0], acc[mf][nf][1]);
                *(float2*)(d0 + 8 * ldC) = make_float2(acc[mf][nf][2], acc[mf][nf][3]);
            } else {
#pragma unroll
                for (int h = 0; h < 2; h++) {
                    float v0 = acc[mf][nf][2*h], v1 = acc[mf][nf][2*h+1];
                    float h0 = __half2float(__float2half_rn(v0));
                    float h1 = __half2float(__float2half_rn(v1));
                    size_t idx = (size_t)z * strideC + (size_t)(r0 + h * 8) * ldC + col;
                    *(uint32_t*)(Chi + idx) = pack2h(v0, v1);
                    *(uint32_t*)(Clo + idx) = pack2h(v0 - h0, v1 - h1);
                }
            }
        }
    }
}

// ============================================================
__global__ void __launch_bounds__(256) ln_kernel(
    const float* __restrict__ x, const float* __restrict__ gamma,
    const float* __restrict__ beta, h16* __restrict__ xnhi, h16* __restrict__ xnlo)
{
    __shared__ float sx[32][NC + 1];
    __shared__ float psum[8][33], psq[8][33];
    __shared__ float smu[32], srs[32];
    int b = blockIdx.y, n0 = blockIdx.x * 32;
    const float* xb = x + (size_t)b * NC * NT;

    for (int i = threadIdx.x; i < NC * 32; i += 256) {
        int c = i >> 5, t = i & 31;
        sx[t][c] = xb[(size_t)c * NT + n0 + t];
    }
    __syncthreads();
    int t = threadIdx.x & 31, g = threadIdx.x >> 5;
    float s0 = 0.f, s1 = 0.f;
#pragma unroll
    for (int j = 0; j < 32; j++) { float v = sx[t][g * 32 + j]; s0 += v; s1 += v * v; }
    psum[g][t] = s0; psq[g][t] = s1;
    __syncthreads();
    if (threadIdx.x < 32) {
        float a = 0.f, bb = 0.f;
#pragma unroll
        for (int j = 0; j < 8; j++) { a += psum[j][threadIdx.x]; bb += psq[j][threadIdx.x]; }
        float mu = a * (1.0f / NC);
        smu[threadIdx.x] = mu;
        srs[threadIdx.x] = rsqrtf(bb * (1.0f / NC) - mu * mu + 1e-5f);
    }
    __syncthreads();
    size_t base = ((size_t)b * NT + n0) * NC;
    for (int i = threadIdx.x; i < NC * 32; i += 256) {
        int tok = i >> 8, c = i & 255;
        float r = (sx[tok][c] - smu[tok]) * srs[tok] * gamma[c] + beta[c];
        float h = __half2float(__float2half_rn(r));
        xnhi[base + (size_t)tok * NC + c] = __float2half_rn(r);
        xnlo[base + (size_t)tok * NC + c] = __float2half_rn(r - h);
    }
}

__global__ void prep_kernel(
    const float* __restrict__ Wq, const float* __restrict__ Wk, const float* __restrict__ Wv,
    h16* qh, h16* ql, h16* kh, h16* kl, h16* vh, h16* vl)
{
    int n = blockIdx.x, k = threadIdx.x;
    size_t src = (size_t)k * NC + n, dst = (size_t)n * NC + k;
    float v, h;
    v = Wq[src]; h = __half2float(__float2half_rn(v)); qh[dst] = __float2half_rn(v); ql[dst] = __float2half_rn(v - h);
    v = Wk[src]; h = __half2float(__float2half_rn(v)); kh[dst] = __float2half_rn(v); kl[dst] = __float2half_rn(v - h);
    v = Wv[src]; h = __half2float(__float2half_rn(v)); vh[dst] = __float2half_rn(v); vl[dst] = __float2half_rn(v - h);
}

// mix: attn = a1*softmax + a2*relu^2, fp16 hi-only out
__global__ void __launch_bounds__(256) mix_kernel(
    const float* __restrict__ w1, const float* __restrict__ w2,
    const float* __restrict__ S, h16* __restrict__ ahi)
{
    size_t ro = ((size_t)blockIdx.y * NT + blockIdx.x) * NT;
    const float4* row4 = (const float4*)(S + ro);
    int tid = threadIdx.x;
    __shared__ float sred[8];

    float4 v[4];
    float mx = -1e30f;
#pragma unroll
    for (int g = 0; g < 4; g++) {
        v[g] = row4[g * 256 + tid];
        mx = fmaxf(mx, fmaxf(fmaxf(v[g].x, v[g].y), fmaxf(v[g].z, v[g].w)));
    }
#pragma unroll
    for (int o = 16; o; o >>= 1) mx = fmaxf(mx, __shfl_xor_sync(0xffffffffu, mx, o));
    if ((tid & 31) == 0) sred[tid >> 5] = mx;
    __syncthreads();
    mx = sred[0];
#pragma unroll
    for (int i = 1; i < 8; i++) mx = fmaxf(mx, sred[i]);
    __syncthreads();

    float4 e[4];
    float sum = 0.f;
#pragma unroll
    for (int g = 0; g < 4; g++) {
        e[g].x = __expf(v[g].x - mx); e[g].y = __expf(v[g].y - mx);
        e[g].z = __expf(v[g].z - mx); e[g].w = __expf(v[g].w - mx);
        sum += e[g].x + e[g].y + e[g].z + e[g].w;
    }
#pragma unroll
    for (int o = 16; o; o >>= 1) sum += __shfl_xor_sync(0xffffffffu, sum, o);
    if ((tid & 31) == 0) sred[tid >> 5] = sum;
    __syncthreads();
    sum = 0.f;
#pragma unroll
    for (int i = 0; i < 8; i++) sum += sred[i];

    float e1 = __expf(w1[0]), e2 = __expf(w2[0]);
    float a1 = e1 / (e1 + e2), a2 = e2 / (e1 + e2);
    float inv = a1 / sum;

    uint2* oh = (uint2*)(ahi + ro);
#pragma unroll
    for (int g = 0; g < 4; g++) {
        float p0 = e[g].x * inv + a2 * fmaxf(v[g].x, 0.f) * fmaxf(v[g].x, 0.f);
        float p1 = e[g].y * inv + a2 * fmaxf(v[g].y, 0.f) * fmaxf(v[g].y, 0.f);
        float p2 = e[g].z * inv + a2 * fmaxf(v[g].z, 0.f) * fmaxf(v[g].z, 0.f);
        float p3 = e[g].w * inv + a2 * fmaxf(v[g].w, 0.f) * fmaxf(v[g].w, 0.f);
        oh[g * 256 + tid] = make_uint2(pack2h(p0, p1), pack2h(p2, p3));
    }
}

__global__ void out_kernel(const float* __restrict__ o, const h16* __restrict__ xnhi,
                           const h16* __restrict__ xnlo, float* __restrict__ out)
{
    __shared__ float tile[32][33];
    int b = blockIdx.z, n0 = blockIdx.x * 32, c0 = blockIdx.y * 32;
    for (int r = threadIdx.y; r < 32; r += 8) {
        size_t idx = ((size_t)b * NT + n0 + r) * NC + c0 + threadIdx.x;
        tile[r][threadIdx.x] = o[idx] + __half2float(xnhi[idx]) + __half2float(xnlo[idx]);
    }
    __syncthreads();
    for (int r = threadIdx.y; r < 32; r += 8)
        out[((size_t)b * NC + c0 + r) * NT + n0 + threadIdx.x] = tile[threadIdx.x][r];
}

// ============================================================
extern "C" void kernel_launch(void* const* d_in, const int* in_sizes, int n_in,
                              void* d_out, int out_size)
{
    const float* x     = (const float*)d_in[0];
    const float* gamma = (const float*)d_in[1];
    const float* beta  = (const float*)d_in[2];
    const float* Wq    = (const float*)d_in[3];
    const float* Wk    = (const float*)d_in[4];
    const float* Wv    = (const float*)d_in[5];
    const float* w1    = (const float*)d_in[6];
    const float* w2    = (const float*)d_in[7];
    float* out = (float*)d_out;

    h16 *xnhi, *xnlo, *qhi, *qlo, *khi, *klo, *vThi, *vTlo;
    h16 *wqhi, *wqlo, *wkhi, *wklo, *wvhi, *wvlo, *ahi;
    float *s, *o;
    cudaGetSymbolAddress((void**)&xnhi, g_xnhi); cudaGetSymbolAddress((void**)&xnlo, g_xnlo);
    cudaGetSymbolAddress((void**)&qhi,  g_qhi);  cudaGetSymbolAddress((void**)&qlo,  g_qlo);
    cudaGetSymbolAddress((void**)&khi,  g_khi);  cudaGetSymbolAddress((void**)&klo,  g_klo);
    cudaGetSymbolAddress((void**)&vThi, g_vThi); cudaGetSymbolAddress((void**)&vTlo, g_vTlo);
    cudaGetSymbolAddress((void**)&wqhi, g_wqhi); cudaGetSymbolAddress((void**)&wqlo, g_wqlo);
    cudaGetSymbolAddress((void**)&wkhi, g_wkhi); cudaGetSymbolAddress((void**)&wklo, g_wklo);
    cudaGetSymbolAddress((void**)&wvhi, g_wvhi); cudaGetSymbolAddress((void**)&wvlo, g_wvlo);
    cudaGetSymbolAddress((void**)&ahi,  g_ahi);
    cudaGetSymbolAddress((void**)&s, g_s); cudaGetSymbolAddress((void**)&o, g_o);

    cudaFuncSetAttribute((const void*)mma_gemm<1,3>, cudaFuncAttributeMaxDynamicSharedMemorySize, 65536);
    cudaFuncSetAttribute((const void*)mma_gemm<0,1>, cudaFuncAttributeMaxDynamicSharedMemorySize, 65536);

    // 1) LayerNorm -> xn pair
    ln_kernel<<<dim3(NT / 32, NB), 256>>>(x, gamma, beta, xnhi, xnlo);
    // 2) weight transpose+split
    prep_kernel<<<NC, NC>>>(Wq, Wk, Wv, wqhi, wqlo, wkhi, wklo, wvhi, wvlo);
    // 3-5) Q, K, V^T projections (3-product, pair out)
    mma_gemm<1,3><<<dim3(2, 128, 1), 256, 65536>>>(
        xnhi, xnlo, NC, 0, wqhi, wqlo, NC, 0, nullptr, qhi, qlo, NC, 0, NC);
    mma_gemm<1,3><<<dim3(2, 128, 1), 256, 65536>>>(
        xnhi, xnlo, NC, 0, wkhi, wklo, NC, 0, nullptr, khi, klo, NC, 0, NC);
    mma_gemm<1,3><<<dim3(128, 2, 1), 256, 65536>>>(
        wvhi, wvlo, NC, 0, xnhi, xnlo, NC, 0, nullptr, vThi, vTlo, (long)NB * NT, 0, NC);
    // 6) S = Q K^T (1-product pure fp16)  <- ncu 6th launch
    mma_gemm<0,1><<<dim3(32, 32, NB), 256, 65536>>>(
        qhi, nullptr, NC, (long)NT * NC, khi, nullptr, NC, (long)NT * NC,
        s, nullptr, nullptr, NT, (long)NT * NT, NC);
    // 7) attn mix -> fp16 hi only
    mix_kernel<<<dim3(NT, NB), 256>>>(w1, w2, s, ahi);
    // 8) O = attn @ V (1-product pure fp16)
    mma_gemm<0,1><<<dim3(2, 32, NB), 256, 65536>>>(
        ahi, nullptr, NT, (long)NT * NT, vThi, nullptr, (long)NB * NT, NT,
        o, nullptr, nullptr, NC, (long)NT * NC, NT);
    // 9) transpose + residual
    out_kernel<<<dim3(NT / 32, NC / 32, NB), dim3(32, 8)>>>(o, xnhi, xnlo, out);
}

// round 11
// speedup vs baseline: 2.2110x; 1.0524x over previous
#include <cuda_runtime.h>
#include <cuda_fp16.h>
#include <math.h>
#include <stdint.h>

#define NB 4
#define NC 256
#define NT 4096

typedef __half h16;

__device__ h16   g_xnhi[NB * NT * NC];
__device__ h16   g_xnlo[NB * NT * NC];
__device__ h16   g_qhi [NB * NT * NC];
__device__ h16   g_khi [NB * NT * NC];
__device__ h16   g_vThi[NC * NB * NT];
__device__ float g_s   [(size_t)NB * NT * NT];
__device__ h16   g_ahi [(size_t)NB * NT * NT];
__device__ float g_o   [NB * NT * NC];
__device__ h16   g_wqhi[NC * NC], g_wqlo[NC * NC];
__device__ h16   g_wkhi[NC * NC], g_wklo[NC * NC];
__device__ h16   g_wvhi[NC * NC], g_wvlo[NC * NC];

__device__ __forceinline__ uint32_t smem_u32(const void* p) {
    uint32_t a;
    asm("{ .reg .u64 t; cvta.to.shared.u64 t, %1; cvt.u32.u64 %0, t; }" : "=r"(a) : "l"(p));
    return a;
}
__device__ __forceinline__ void cp16(uint32_t s, const void* g) {
    asm volatile("cp.async.cg.shared.global [%0], [%1], 16;" :: "r"(s), "l"(g));
}
__device__ __forceinline__ void cp_commit() { asm volatile("cp.async.commit_group;" ::: "memory"); }
template <int N> __device__ __forceinline__ void cp_wait() {
    asm volatile("cp.async.wait_group %0;" :: "n"(N) : "memory");
}
__device__ __forceinline__ void ldm_x4(uint32_t* r, uint32_t addr) {
    asm volatile("ldmatrix.sync.aligned.m8n8.x4.shared.b16 {%0,%1,%2,%3}, [%4];"
                 : "=r"(r[0]), "=r"(r[1]), "=r"(r[2]), "=r"(r[3]) : "r"(addr));
}
__device__ __forceinline__ void mma16816(float* d, const uint32_t* a, const uint32_t* b) {
    asm volatile(
        "mma.sync.aligned.m16n8k16.row.col.f32.f16.f16.f32 "
        "{%0,%1,%2,%3}, {%4,%5,%6,%7}, {%8,%9}, {%0,%1,%2,%3};"
        : "+f"(d[0]), "+f"(d[1]), "+f"(d[2]), "+f"(d[3])
        : "r"(a[0]), "r"(a[1]), "r"(a[2]), "r"(a[3]), "r"(b[0]), "r"(b[1]));
}
__device__ __forceinline__ uint32_t swz(uint32_t off) { return off ^ ((off >> 3) & 0x70); }
__device__ __forceinline__ uint32_t pack2h(float a, float b) {
    return (uint32_t)__half_as_ushort(__float2half_rn(a))
         | ((uint32_t)__half_as_ushort(__float2half_rn(b)) << 16);
}

// ============================================================
// split-fp16 GEMM.
//   NPROD=2: Ahi*Bhi + Ahi*Blo  (A hi only, B pair)
//   NPROD=1: Ahi*Bhi            (pure fp16)
// BM=BN=128, BK=32, 256 thr (8 warps 2x4), warp tile 64x32,
// 3-stage cp.async pipeline (96KB smem), 2 CTA/SM.
// EPI=0: fp32 out. EPI=1: fp16 hi-only out.
// ============================================================
template <int EPI, int NPROD>
__global__ void __launch_bounds__(256, 2) mma_gemm(
    const h16* __restrict__ Ahi, long ldA, long strideA,
    const h16* __restrict__ Bhi, const h16* __restrict__ Blo, long ldB, long strideB,
    float* __restrict__ Cf, h16* __restrict__ Chi,
    long ldC, long strideC, int K)
{
    extern __shared__ char dyn[];
    const uint32_t sbase = smem_u32(dyn);
    const int tid = threadIdx.x;
    const int wid = tid >> 5, lane = tid & 31;
    const int warpM = wid & 1, warpN = wid >> 1;

    const int z = blockIdx.z;
    const long m0 = (long)blockIdx.y * 128;
    const long n0 = (long)blockIdx.x * 128;
    const h16* pAh = Ahi + (size_t)z * strideA + (size_t)m0 * ldA;
    const h16* pBh = Bhi + (size_t)z * strideB + (size_t)n0 * ldB;
    const h16* pBl = (NPROD >= 2) ? Blo + (size_t)z * strideB + (size_t)n0 * ldB : nullptr;

    const int nk = K / 32;
    const uint32_t STAGE = 32768;

    auto load_stage = [&](int st, int ks) {
        uint32_t base = sbase + (uint32_t)st * STAGE;
#pragma unroll
        for (int i = 0; i < 4; i++) {
            int cid = tid + i * 256;
            int m = cid >> 3, c = cid & 7;
            int part = c >> 2, kc = c & 3;
            uint32_t off = swz((uint32_t)(m * 128 + c * 16));
            if (part == 0)
                cp16(base + off, pAh + (size_t)m * ldA + ks * 32 + kc * 8);
            if (NPROD >= 2 || part == 0)
                cp16(base + 16384u + off, (part ? pBl : pBh) + (size_t)m * ldB + ks * 32 + kc * 8);
        }
    };

    float acc[4][4][4] = {};
    load_stage(0, 0); cp_commit();
    if (nk > 1) { load_stage(1, 1); cp_commit(); }

    const int lr = lane & 7, lg = lane >> 3;

    for (int ks = 0; ks < nk; ks++) {
        if (ks + 1 < nk) cp_wait<1>(); else cp_wait<0>();
        __syncthreads();
        // safe: stage (ks+2)%3 == stage (ks-1)%3, consumed by all warps
        // before the sync above.
        if (ks + 2 < nk) { load_stage((ks + 2) % 3, ks + 2); cp_commit(); }

        uint32_t aBase = sbase + (uint32_t)(ks % 3) * STAGE;
        uint32_t bBase = aBase + 16384u;

#pragma unroll
        for (int kst = 0; kst < 2; kst++) {
            const uint32_t kb = kst * 32;
            uint32_t ah[4][4];
#pragma unroll
            for (int mf = 0; mf < 4; mf++) {
                uint32_t row = warpM * 64 + mf * 16 + lr + ((lg & 1) << 3);
                ldm_x4(ah[mf], aBase + swz(row * 128 + kb + ((lg >> 1) << 4)));
            }
            uint32_t bh[4][2];
#pragma unroll
            for (int p = 0; p < 2; p++) {
                uint32_t row = warpN * 32 + p * 16 + lr + ((lg >> 1) << 3);
                uint32_t t[4];
                ldm_x4(t, bBase + swz(row * 128 + kb + ((lg & 1) << 4)));
                bh[2*p][0] = t[0]; bh[2*p][1] = t[1];
                bh[2*p+1][0] = t[2]; bh[2*p+1][1] = t[3];
            }
#pragma unroll
            for (int mf = 0; mf < 4; mf++)
#pragma unroll
                for (int nf = 0; nf < 4; nf++)
                    mma16816(acc[mf][nf], ah[mf], bh[nf]);

            if (NPROD >= 2) {
                uint32_t bl[4][2];
#pragma unroll
                for (int p = 0; p < 2; p++) {
                    uint32_t row = warpN * 32 + p * 16 + lr + ((lg >> 1) << 3);
                    uint32_t t[4];
                    ldm_x4(t, bBase + swz(row * 128 + 64 + kb + ((lg & 1) << 4)));
                    bl[2*p][0] = t[0]; bl[2*p][1] = t[1];
                    bl[2*p+1][0] = t[2]; bl[2*p+1][1] = t[3];
                }
#pragma unroll
                for (int mf = 0; mf < 4; mf++)
#pragma unroll
                    for (int nf = 0; nf < 4; nf++)
                        mma16816(acc[mf][nf], ah[mf], bl[nf]);
            }
        }
    }

    const int qr = lane >> 2, qc = (lane & 3) * 2;
#pragma unroll
    for (int mf = 0; mf < 4; mf++) {
#pragma unroll
        for (int nf = 0; nf < 4; nf++) {
            long r0  = m0 + warpM * 64 + mf * 16 + qr;
            long col = n0 + warpN * 32 + nf * 8 + qc;
            if (EPI == 0) {
                float* d0 = Cf + (size_t)z * strideC + (size_t)r0 * ldC + col;
                *(float2*)d0             = make_float2(acc[mf][nf][0], acc[mf][nf][1]);
                *(float2*)(d0 + 8 * ldC) = make_float2(acc[mf][nf][2], acc[mf][nf][3]);
            } else {
#pragma unroll
                for (int h = 0; h < 2; h++) {
                    size_t idx = (size_t)z * strideC + (size_t)(r0 + h * 8) * ldC + col;
                    *(uint32_t*)(Chi + idx) = pack2h(acc[mf][nf][2*h], acc[mf][nf][2*h+1]);
                }
            }
        }
    }
}

// ============================================================
__global__ void __launch_bounds__(256) ln_kernel(
    const float* __restrict__ x, const float* __restrict__ gamma,
    const float* __restrict__ beta, h16* __restrict__ xnhi, h16* __restrict__ xnlo)
{
    __shared__ float sx[32][NC + 1];
    __shared__ float psum[8][33], psq[8][33];
    __shared__ float smu[32], srs[32];
    int b = blockIdx.y, n0 = blockIdx.x * 32;
    const float* xb = x + (size_t)b * NC * NT;

    for (int i = threadIdx.x; i < NC * 32; i += 256) {
        int c = i >> 5, t = i & 31;
        sx[t][c] = xb[(size_t)c * NT + n0 + t];
    }
    __syncthreads();
    int t = threadIdx.x & 31, g = threadIdx.x >> 5;
    float s0 = 0.f, s1 = 0.f;
#pragma unroll
    for (int j = 0; j < 32; j++) { float v = sx[t][g * 32 + j]; s0 += v; s1 += v * v; }
    psum[g][t] = s0; psq[g][t] = s1;
    __syncthreads();
    if (threadIdx.x < 32) {
        float a = 0.f, bb = 0.f;
#pragma unroll
        for (int j = 0; j < 8; j++) { a += psum[j][threadIdx.x]; bb += psq[j][threadIdx.x]; }
        float mu = a * (1.0f / NC);
        smu[threadIdx.x] = mu;
        srs[threadIdx.x] = rsqrtf(bb * (1.0f / NC) - mu * mu + 1e-5f);
    }
    __syncthreads();
    size_t base = ((size_t)b * NT + n0) * NC;
    for (int i = threadIdx.x; i < NC * 32; i += 256) {
        int tok = i >> 8, c = i & 255;
        float r = (sx[tok][c] - smu[tok]) * srs[tok] * gamma[c] + beta[c];
        float h = __half2float(__float2half_rn(r));
        xnhi[base + (size_t)tok * NC + c] = __float2half_rn(r);
        xnlo[base + (size_t)tok * NC + c] = __float2half_rn(r - h);
    }
}

__global__ void prep_kernel(
    const float* __restrict__ Wq, const float* __restrict__ Wk, const float* __restrict__ Wv,
    h16* qh, h16* ql, h16* kh, h16* kl, h16* vh, h16* vl)
{
    int n = blockIdx.x, k = threadIdx.x;
    size_t src = (size_t)k * NC + n, dst = (size_t)n * NC + k;
    float v, h;
    v = Wq[src]; h = __half2float(__float2half_rn(v)); qh[dst] = __float2half_rn(v); ql[dst] = __float2half_rn(v - h);
    v = Wk[src]; h = __half2float(__float2half_rn(v)); kh[dst] = __float2half_rn(v); kl[dst] = __float2half_rn(v - h);
    v = Wv[src]; h = __half2float(__float2half_rn(v)); vh[dst] = __float2half_rn(v); vl[dst] = __float2half_rn(v - h);
}

// mix: attn = a1*softmax + a2*relu^2, fp16 hi-only out
__global__ void __launch_bounds__(256) mix_kernel(
    const float* __restrict__ w1, const float* __restrict__ w2,
    const float* __restrict__ S, h16* __restrict__ ahi)
{
    size_t ro = ((size_t)blockIdx.y * NT + blockIdx.x) * NT;
    const float4* row4 = (const float4*)(S + ro);
    int tid = threadIdx.x;
    __shared__ float sred[8];

    float4 v[4];
    float mx = -1e30f;
#pragma unroll
    for (int g = 0; g < 4; g++) {
        v[g] = row4[g * 256 + tid];
        mx = fmaxf(mx, fmaxf(fmaxf(v[g].x, v[g].y), fmaxf(v[g].z, v[g].w)));
    }
#pragma unroll
    for (int o = 16; o; o >>= 1) mx = fmaxf(mx, __shfl_xor_sync(0xffffffffu, mx, o));
    if ((tid & 31) == 0) sred[tid >> 5] = mx;
    __syncthreads();
    mx = sred[0];
#pragma unroll
    for (int i = 1; i < 8; i++) mx = fmaxf(mx, sred[i]);
    __syncthreads();

    float4 e[4];
    float sum = 0.f;
#pragma unroll
    for (int g = 0; g < 4; g++) {
        e[g].x = __expf(v[g].x - mx); e[g].y = __expf(v[g].y - mx);
        e[g].z = __expf(v[g].z - mx); e[g].w = __expf(v[g].w - mx);
        sum += e[g].x + e[g].y + e[g].z + e[g].w;
    }
#pragma unroll
    for (int o = 16; o; o >>= 1) sum += __shfl_xor_sync(0xffffffffu, sum, o);
    if ((tid & 31) == 0) sred[tid >> 5] = sum;
    __syncthreads();
    sum = 0.f;
#pragma unroll
    for (int i = 0; i < 8; i++) sum += sred[i];

    float e1 = __expf(w1[0]), e2 = __expf(w2[0]);
    float a1 = e1 / (e1 + e2), a2 = e2 / (e1 + e2);
    float inv = a1 / sum;

    uint2* oh = (uint2*)(ahi + ro);
#pragma unroll
    for (int g = 0; g < 4; g++) {
        float p0 = e[g].x * inv + a2 * fmaxf(v[g].x, 0.f) * fmaxf(v[g].x, 0.f);
        float p1 = e[g].y * inv + a2 * fmaxf(v[g].y, 0.f) * fmaxf(v[g].y, 0.f);
        float p2 = e[g].z * inv + a2 * fmaxf(v[g].z, 0.f) * fmaxf(v[g].z, 0.f);
        float p3 = e[g].w * inv + a2 * fmaxf(v[g].w, 0.f) * fmaxf(v[g].w, 0.f);
        oh[g * 256 + tid] = make_uint2(pack2h(p0, p1), pack2h(p2, p3));
    }
}

__global__ void out_kernel(const float* __restrict__ o, const h16* __restrict__ xnhi,
                           const h16* __restrict__ xnlo, float* __restrict__ out)
{
    __shared__ float tile[32][33];
    int b = blockIdx.z, n0 = blockIdx.x * 32, c0 = blockIdx.y * 32;
    for (int r = threadIdx.y; r < 32; r += 8) {
        size_t idx = ((size_t)b * NT + n0 + r) * NC + c0 + threadIdx.x;
        tile[r][threadIdx.x] = o[idx] + __half2float(xnhi[idx]) + __half2float(xnlo[idx]);
    }
    __syncthreads();
    for (int r = threadIdx.y; r < 32; r += 8)
        out[((size_t)b * NC + c0 + r) * NT + n0 + threadIdx.x] = tile[threadIdx.x][r];
}

// ============================================================
extern "C" void kernel_launch(void* const* d_in, const int* in_sizes, int n_in,
                              void* d_out, int out_size)
{
    const float* x     = (const float*)d_in[0];
    const float* gamma = (const float*)d_in[1];
    const float* beta  = (const float*)d_in[2];
    const float* Wq    = (const float*)d_in[3];
    const float* Wk    = (const float*)d_in[4];
    const float* Wv    = (const float*)d_in[5];
    const float* w1    = (const float*)d_in[6];
    const float* w2    = (const float*)d_in[7];
    float* out = (float*)d_out;

    h16 *xnhi, *xnlo, *qhi, *khi, *vThi;
    h16 *wqhi, *wqlo, *wkhi, *wklo, *wvhi, *wvlo, *ahi;
    float *s, *o;
    cudaGetSymbolAddress((void**)&xnhi, g_xnhi); cudaGetSymbolAddress((void**)&xnlo, g_xnlo);
    cudaGetSymbolAddress((void**)&qhi,  g_qhi);
    cudaGetSymbolAddress((void**)&khi,  g_khi);
    cudaGetSymbolAddress((void**)&vThi, g_vThi);
    cudaGetSymbolAddress((void**)&wqhi, g_wqhi); cudaGetSymbolAddress((void**)&wqlo, g_wqlo);
    cudaGetSymbolAddress((void**)&wkhi, g_wkhi); cudaGetSymbolAddress((void**)&wklo, g_wklo);
    cudaGetSymbolAddress((void**)&wvhi, g_wvhi); cudaGetSymbolAddress((void**)&wvlo, g_wvlo);
    cudaGetSymbolAddress((void**)&ahi,  g_ahi);
    cudaGetSymbolAddress((void**)&s, g_s); cudaGetSymbolAddress((void**)&o, g_o);

    cudaFuncSetAttribute((const void*)mma_gemm<1,2>, cudaFuncAttributeMaxDynamicSharedMemorySize, 98304);
    cudaFuncSetAttribute((const void*)mma_gemm<0,1>, cudaFuncAttributeMaxDynamicSharedMemorySize, 98304);

    // 1) LayerNorm -> xn pair
    ln_kernel<<<dim3(NT / 32, NB), 256>>>(x, gamma, beta, xnhi, xnlo);
    // 2) weight transpose+split
    prep_kernel<<<NC, NC>>>(Wq, Wk, Wv, wqhi, wqlo, wkhi, wklo, wvhi, wvlo);
    // 3-5) Q, K, V^T projections (2-product: xn_hi x W-pair, hi out)
    mma_gemm<1,2><<<dim3(2, 128, 1), 256, 98304>>>(
        xnhi, NC, 0, wqhi, wqlo, NC, 0, nullptr, qhi, NC, 0, NC);
    mma_gemm<1,2><<<dim3(2, 128, 1), 256, 98304>>>(
        xnhi, NC, 0, wkhi, wklo, NC, 0, nullptr, khi, NC, 0, NC);
    mma_gemm<1,2><<<dim3(128, 2, 1), 256, 98304>>>(
        wvhi, NC, 0, xnhi, xnlo, NC, 0, nullptr, vThi, (long)NB * NT, 0, NC);
    // 6) S = Q K^T (pure fp16)  <- ncu 6th launch
    mma_gemm<0,1><<<dim3(32, 32, NB), 256, 98304>>>(
        qhi, NC, (long)NT * NC, khi, nullptr, NC, (long)NT * NC,
        s, nullptr, NT, (long)NT * NT, NC);
    // 7) attn mix -> fp16 hi only
    mix_kernel<<<dim3(NT, NB), 256>>>(w1, w2, s, ahi);
    // 8) O = attn @ V (pure fp16)
    mma_gemm<0,1><<<dim3(2, 32, NB), 256, 98304>>>(
        ahi, NT, (long)NT * NT, vThi, nullptr, (long)NB * NT, NT,
        o, nullptr, NC, (long)NT * NC, NT);
    // 9) transpose + residual
    out_kernel<<<dim3(NT / 32, NC / 32, NB), dim3(32, 8)>>>(o, xnhi, xnlo, out);
}

// round 12
// speedup vs baseline: 2.4541x; 1.1100x over previous
#include <cuda_runtime.h>
#include <cuda_fp16.h>
#include <math.h>
#include <stdint.h>

#define NB 4
#define NC 256
#define NT 4096

typedef __half h16;

__device__ h16   g_xnhi[NB * NT * NC];
__device__ h16   g_xnlo[NB * NT * NC];
__device__ h16   g_qhi [NB * NT * NC];
__device__ h16   g_khi [NB * NT * NC];
__device__ h16   g_vThi[NC * NB * NT];
__device__ float g_s   [(size_t)NB * NT * NT];
__device__ h16   g_ahi [(size_t)NB * NT * NT];
__device__ float g_o   [NB * NT * NC];
__device__ h16   g_wqhi[NC * NC], g_wqlo[NC * NC];
__device__ h16   g_wkhi[NC * NC], g_wklo[NC * NC];
__device__ h16   g_wvhi[NC * NC], g_wvlo[NC * NC];

__device__ __forceinline__ uint32_t smem_u32(const void* p) {
    uint32_t a;
    asm("{ .reg .u64 t; cvta.to.shared.u64 t, %1; cvt.u32.u64 %0, t; }" : "=r"(a) : "l"(p));
    return a;
}
__device__ __forceinline__ void cp16(uint32_t s, const void* g) {
    asm volatile("cp.async.cg.shared.global [%0], [%1], 16;" :: "r"(s), "l"(g));
}
__device__ __forceinline__ void cp_commit() { asm volatile("cp.async.commit_group;" ::: "memory"); }
template <int N> __device__ __forceinline__ void cp_wait() {
    asm volatile("cp.async.wait_group %0;" :: "n"(N) : "memory");
}
__device__ __forceinline__ void ldm_x4(uint32_t* r, uint32_t addr) {
    asm volatile("ldmatrix.sync.aligned.m8n8.x4.shared.b16 {%0,%1,%2,%3}, [%4];"
                 : "=r"(r[0]), "=r"(r[1]), "=r"(r[2]), "=r"(r[3]) : "r"(addr));
}
__device__ __forceinline__ void mma16816(float* d, const uint32_t* a, const uint32_t* b) {
    asm volatile(
        "mma.sync.aligned.m16n8k16.row.col.f32.f16.f16.f32 "
        "{%0,%1,%2,%3}, {%4,%5,%6,%7}, {%8,%9}, {%0,%1,%2,%3};"
        : "+f"(d[0]), "+f"(d[1]), "+f"(d[2]), "+f"(d[3])
        : "r"(a[0]), "r"(a[1]), "r"(a[2]), "r"(a[3]), "r"(b[0]), "r"(b[1]));
}
__device__ __forceinline__ uint32_t swz(uint32_t off) { return off ^ ((off >> 3) & 0x70); }
__device__ __forceinline__ uint32_t pack2h(float a, float b) {
    return (uint32_t)__half_as_ushort(__float2half_rn(a))
         | ((uint32_t)__half_as_ushort(__float2half_rn(b)) << 16);
}

// ============================================================
// split-fp16 GEMM, BK=64, clean 128B rows.
//   NPROD=1: Ahi*Bhi                 3 stages x 32KB
//   NPROD=2: Ahi*Bhi + Ahi*Blo       2 stages x 48KB
// BM=BN=128, 256 thr (8 warps 2x4), warp tile 64x32, 2 CTA/SM.
// EPI=0: fp32 out. EPI=1: fp16 hi out.
// ============================================================
template <int EPI, int NPROD>
__global__ void __launch_bounds__(256, 2) mma_gemm(
    const h16* __restrict__ Ahi, long ldA, long strideA,
    const h16* __restrict__ Bhi, const h16* __restrict__ Blo, long ldB, long strideB,
    float* __restrict__ Cf, h16* __restrict__ Chi,
    long ldC, long strideC, int K)
{
    extern __shared__ char dyn[];
    const uint32_t sbase = smem_u32(dyn);
    const int tid = threadIdx.x;
    const int wid = tid >> 5, lane = tid & 31;
    const int warpM = wid & 1, warpN = wid >> 1;

    constexpr int NSTAGE = (NPROD == 1) ? 3 : 2;
    constexpr uint32_t PLANE = 16384;
    constexpr uint32_t STAGE = PLANE * (1 + NPROD);   // A + B planes

    const int z = blockIdx.z;
    const long m0 = (long)blockIdx.y * 128;
    const long n0 = (long)blockIdx.x * 128;
    const h16* pAh = Ahi + (size_t)z * strideA + (size_t)m0 * ldA;
    const h16* pBh = Bhi + (size_t)z * strideB + (size_t)n0 * ldB;
    const h16* pBl = (NPROD >= 2) ? Blo + (size_t)z * strideB + (size_t)n0 * ldB : nullptr;

    const int nk = K / 64;

    auto load_stage = [&](int st, int ks) {
        uint32_t base = sbase + (uint32_t)st * STAGE;
#pragma unroll
        for (int i = 0; i < 4; i++) {
            int cid = tid + i * 256;            // 0..1023
            int m = cid >> 3, c = cid & 7;      // row, 16B chunk in 128B row
            uint32_t off = swz((uint32_t)(m * 128 + c * 16));
            cp16(base + off,          pAh + (size_t)m * ldA + ks * 64 + c * 8);
            cp16(base + PLANE + off,  pBh + (size_t)m * ldB + ks * 64 + c * 8);
            if (NPROD >= 2)
                cp16(base + 2 * PLANE + off, pBl + (size_t)m * ldB + ks * 64 + c * 8);
        }
    };

    float acc[4][4][4] = {};
    load_stage(0, 0); cp_commit();
    if (NSTAGE == 3 && nk > 1) { load_stage(1, 1); cp_commit(); }

    const int lr = lane & 7, lg = lane >> 3;

    for (int ks = 0; ks < nk; ks++) {
        if (NSTAGE == 3) {
            if (ks + 1 < nk) cp_wait<1>(); else cp_wait<0>();
            __syncthreads();
            if (ks + 2 < nk) { load_stage((ks + 2) % 3, ks + 2); cp_commit(); }
        } else {
            cp_wait<0>();
            __syncthreads();
            if (ks + 1 < nk) { load_stage((ks + 1) & 1, ks + 1); cp_commit(); }
        }

        uint32_t aBase = sbase + (uint32_t)(ks % NSTAGE) * STAGE;
        uint32_t bBase = aBase + PLANE;
        uint32_t lBase = aBase + 2 * PLANE;

#pragma unroll
        for (int kst = 0; kst < 4; kst++) {
            const uint32_t kb = kst * 32;
            uint32_t ah[4][4];
#pragma unroll
            for (int mf = 0; mf < 4; mf++) {
                uint32_t row = warpM * 64 + mf * 16 + lr + ((lg & 1) << 3);
                ldm_x4(ah[mf], aBase + swz(row * 128 + kb + ((lg >> 1) << 4)));
            }
            uint32_t bh[4][2];
#pragma unroll
            for (int p = 0; p < 2; p++) {
                uint32_t row = warpN * 32 + p * 16 + lr + ((lg >> 1) << 3);
                uint32_t t[4];
                ldm_x4(t, bBase + swz(row * 128 + kb + ((lg & 1) << 4)));
                bh[2*p][0] = t[0]; bh[2*p][1] = t[1];
                bh[2*p+1][0] = t[2]; bh[2*p+1][1] = t[3];
            }
#pragma unroll
            for (int mf = 0; mf < 4; mf++)
#pragma unroll
                for (int nf = 0; nf < 4; nf++)
                    mma16816(acc[mf][nf], ah[mf], bh[nf]);

            if (NPROD >= 2) {
                uint32_t bl[4][2];
#pragma unroll
                for (int p = 0; p < 2; p++) {
                    uint32_t row = warpN * 32 + p * 16 + lr + ((lg >> 1) << 3);
                    uint32_t t[4];
                    ldm_x4(t, lBase + swz(row * 128 + kb + ((lg & 1) << 4)));
                    bl[2*p][0] = t[0]; bl[2*p][1] = t[1];
                    bl[2*p+1][0] = t[2]; bl[2*p+1][1] = t[3];
                }
#pragma unroll
                for (int mf = 0; mf < 4; mf++)
#pragma unroll
                    for (int nf = 0; nf < 4; nf++)
                        mma16816(acc[mf][nf], ah[mf], bl[nf]);
            }
        }
    }

    const int qr = lane >> 2, qc = (lane & 3) * 2;
#pragma unroll
    for (int mf = 0; mf < 4; mf++) {
#pragma unroll
        for (int nf = 0; nf < 4; nf++) {
            long r0  = m0 + warpM * 64 + mf * 16 + qr;
            long col = n0 + warpN * 32 + nf * 8 + qc;
            if (EPI == 0) {
                float* d0 = Cf + (size_t)z * strideC + (size_t)r0 * ldC + col;
                *(float2*)d0             = make_float2(acc[mf][nf][0], acc[mf][nf][1]);
                *(float2*)(d0 + 8 * ldC) = make_float2(acc[mf][nf][2], acc[mf][nf][3]);
            } else {
#pragma unroll
                for (int h = 0; h < 2; h++) {
                    size_t idx = (size_t)z * strideC + (size_t)(r0 + h * 8) * ldC + col;
                    *(uint32_t*)(Chi + idx) = pack2h(acc[mf][nf][2*h], acc[mf][nf][2*h+1]);
                }
            }
        }
    }
}

// ============================================================
__global__ void __launch_bounds__(256) ln_kernel(
    const float* __restrict__ x, const float* __restrict__ gamma,
    const float* __restrict__ beta, h16* __restrict__ xnhi, h16* __restrict__ xnlo)
{
    __shared__ float sx[32][NC + 1];
    __shared__ float psum[8][33], psq[8][33];
    __shared__ float smu[32], srs[32];
    int b = blockIdx.y, n0 = blockIdx.x * 32;
    const float* xb = x + (size_t)b * NC * NT;

    for (int i = threadIdx.x; i < NC * 32; i += 256) {
        int c = i >> 5, t = i & 31;
        sx[t][c] = xb[(size_t)c * NT + n0 + t];
    }
    __syncthreads();
    int t = threadIdx.x & 31, g = threadIdx.x >> 5;
    float s0 = 0.f, s1 = 0.f;
#pragma unroll
    for (int j = 0; j < 32; j++) { float v = sx[t][g * 32 + j]; s0 += v; s1 += v * v; }
    psum[g][t] = s0; psq[g][t] = s1;
    __syncthreads();
    if (threadIdx.x < 32) {
        float a = 0.f, bb = 0.f;
#pragma unroll
        for (int j = 0; j < 8; j++) { a += psum[j][threadIdx.x]; bb += psq[j][threadIdx.x]; }
        float mu = a * (1.0f / NC);
        smu[threadIdx.x] = mu;
        srs[threadIdx.x] = rsqrtf(bb * (1.0f / NC) - mu * mu + 1e-5f);
    }
    __syncthreads();
    size_t base = ((size_t)b * NT + n0) * NC;
    for (int i = threadIdx.x; i < NC * 32; i += 256) {
        int tok = i >> 8, c = i & 255;
        float r = (sx[tok][c] - smu[tok]) * srs[tok] * gamma[c] + beta[c];
        float h = __half2float(__float2half_rn(r));
        xnhi[base + (size_t)tok * NC + c] = __float2half_rn(r);
        xnlo[base + (size_t)tok * NC + c] = __float2half_rn(r - h);
    }
}

__global__ void prep_kernel(
    const float* __restrict__ Wq, const float* __restrict__ Wk, const float* __restrict__ Wv,
    h16* qh, h16* ql, h16* kh, h16* kl, h16* vh, h16* vl)
{
    int n = blockIdx.x, k = threadIdx.x;
    size_t src = (size_t)k * NC + n, dst = (size_t)n * NC + k;
    float v, h;
    v = Wq[src]; h = __half2float(__float2half_rn(v)); qh[dst] = __float2half_rn(v); ql[dst] = __float2half_rn(v - h);
    v = Wk[src]; h = __half2float(__float2half_rn(v)); kh[dst] = __float2half_rn(v); kl[dst] = __float2half_rn(v - h);
    v = Wv[src]; h = __half2float(__float2half_rn(v)); vh[dst] = __float2half_rn(v); vl[dst] = __float2half_rn(v - h);
}

// mix: attn = a1*softmax + a2*relu^2, fp16 hi-only out
__global__ void __launch_bounds__(256) mix_kernel(
    const float* __restrict__ w1, const float* __restrict__ w2,
    const float* __restrict__ S, h16* __restrict__ ahi)
{
    size_t ro = ((size_t)blockIdx.y * NT + blockIdx.x) * NT;
    const float4* row4 = (const float4*)(S + ro);
    int tid = threadIdx.x;
    __shared__ float sred[8];

    float4 v[4];
    float mx = -1e30f;
#pragma unroll
    for (int g = 0; g < 4; g++) {
        v[g] = row4[g * 256 + tid];
        mx = fmaxf(mx, fmaxf(fmaxf(v[g].x, v[g].y), fmaxf(v[g].z, v[g].w)));
    }
#pragma unroll
    for (int o = 16; o; o >>= 1) mx = fmaxf(mx, __shfl_xor_sync(0xffffffffu, mx, o));
    if ((tid & 31) == 0) sred[tid >> 5] = mx;
    __syncthreads();
    mx = sred[0];
#pragma unroll
    for (int i = 1; i < 8; i++) mx = fmaxf(mx, sred[i]);
    __syncthreads();

    float4 e[4];
    float sum = 0.f;
#pragma unroll
    for (int g = 0; g < 4; g++) {
        e[g].x = __expf(v[g].x - mx); e[g].y = __expf(v[g].y - mx);
        e[g].z = __expf(v[g].z - mx); e[g].w = __expf(v[g].w - mx);
        sum += e[g].x + e[g].y + e[g].z + e[g].w;
    }
#pragma unroll
    for (int o = 16; o; o >>= 1) sum += __shfl_xor_sync(0xffffffffu, sum, o);
    if ((tid & 31) == 0) sred[tid >> 5] = sum;
    __syncthreads();
    sum = 0.f;
#pragma unroll
    for (int i = 0; i < 8; i++) sum += sred[i];

    float e1 = __expf(w1[0]), e2 = __expf(w2[0]);
    float a1 = e1 / (e1 + e2), a2 = e2 / (e1 + e2);
    float inv = a1 / sum;

    uint2* oh = (uint2*)(ahi + ro);
#pragma unroll
    for (int g = 0; g < 4; g++) {
        float p0 = e[g].x * inv + a2 * fmaxf(v[g].x, 0.f) * fmaxf(v[g].x, 0.f);
        float p1 = e[g].y * inv + a2 * fmaxf(v[g].y, 0.f) * fmaxf(v[g].y, 0.f);
        float p2 = e[g].z * inv + a2 * fmaxf(v[g].z, 0.f) * fmaxf(v[g].z, 0.f);
        float p3 = e[g].w * inv + a2 * fmaxf(v[g].w, 0.f) * fmaxf(v[g].w, 0.f);
        oh[g * 256 + tid] = make_uint2(pack2h(p0, p1), pack2h(p2, p3));
    }
}

__global__ void out_kernel(const float* __restrict__ o, const h16* __restrict__ xnhi,
                           const h16* __restrict__ xnlo, float* __restrict__ out)
{
    __shared__ float tile[32][33];
    int b = blockIdx.z, n0 = blockIdx.x * 32, c0 = blockIdx.y * 32;
    for (int r = threadIdx.y; r < 32; r += 8) {
        size_t idx = ((size_t)b * NT + n0 + r) * NC + c0 + threadIdx.x;
        tile[r][threadIdx.x] = o[idx] + __half2float(xnhi[idx]) + __half2float(xnlo[idx]);
    }
    __syncthreads();
    for (int r = threadIdx.y; r < 32; r += 8)
        out[((size_t)b * NC + c0 + r) * NT + n0 + threadIdx.x] = tile[threadIdx.x][r];
}

// ============================================================
extern "C" void kernel_launch(void* const* d_in, const int* in_sizes, int n_in,
                              void* d_out, int out_size)
{
    const float* x     = (const float*)d_in[0];
    const float* gamma = (const float*)d_in[1];
    const float* beta  = (const float*)d_in[2];
    const float* Wq    = (const float*)d_in[3];
    const float* Wk    = (const float*)d_in[4];
    const float* Wv    = (const float*)d_in[5];
    const float* w1    = (const float*)d_in[6];
    const float* w2    = (const float*)d_in[7];
    float* out = (float*)d_out;

    h16 *xnhi, *xnlo, *qhi, *khi, *vThi;
    h16 *wqhi, *wqlo, *wkhi, *wklo, *wvhi, *wvlo, *ahi;
    float *s, *o;
    cudaGetSymbolAddress((void**)&xnhi, g_xnhi); cudaGetSymbolAddress((void**)&xnlo, g_xnlo);
    cudaGetSymbolAddress((void**)&qhi,  g_qhi);
    cudaGetSymbolAddress((void**)&khi,  g_khi);
    cudaGetSymbolAddress((void**)&vThi, g_vThi);
    cudaGetSymbolAddress((void**)&wqhi, g_wqhi); cudaGetSymbolAddress((void**)&wqlo, g_wqlo);
    cudaGetSymbolAddress((void**)&wkhi, g_wkhi); cudaGetSymbolAddress((void**)&wklo, g_wklo);
    cudaGetSymbolAddress((void**)&wvhi, g_wvhi); cudaGetSymbolAddress((void**)&wvlo, g_wvlo);
    cudaGetSymbolAddress((void**)&ahi,  g_ahi);
    cudaGetSymbolAddress((void**)&s, g_s); cudaGetSymbolAddress((void**)&o, g_o);

    cudaFuncSetAttribute((const void*)mma_gemm<1,2>, cudaFuncAttributeMaxDynamicSharedMemorySize, 98304);
    cudaFuncSetAttribute((const void*)mma_gemm<0,1>, cudaFuncAttributeMaxDynamicSharedMemorySize, 98304);

    // 1) LayerNorm -> xn pair
    ln_kernel<<<dim3(NT / 32, NB), 256>>>(x, gamma, beta, xnhi, xnlo);
    // 2) weight transpose+split
    prep_kernel<<<NC, NC>>>(Wq, Wk, Wv, wqhi, wqlo, wkhi, wklo, wvhi, wvlo);
    // 3-5) Q, K, V^T projections (2-product: xn_hi x W-pair, hi out)
    mma_gemm<1,2><<<dim3(2, 128, 1), 256, 98304>>>(
        xnhi, NC, 0, wqhi, wqlo, NC, 0, nullptr, qhi, NC, 0, NC);
    mma_gemm<1,2><<<dim3(2, 128, 1), 256, 98304>>>(
        xnhi, NC, 0, wkhi, wklo, NC, 0, nullptr, khi, NC, 0, NC);
    mma_gemm<1,2><<<dim3(128, 2, 1), 256, 98304>>>(
        wvhi, NC, 0, xnhi, xnlo, NC, 0, nullptr, vThi, (long)NB * NT, 0, NC);
    // 6) S = Q K^T (pure fp16)  <- ncu 6th launch
    mma_gemm<0,1><<<dim3(32, 32, NB), 256, 98304>>>(
        qhi, NC, (long)NT * NC, khi, nullptr, NC, (long)NT * NC,
        s, nullptr, NT, (long)NT * NT, NC);
    // 7) attn mix -> fp16 hi only
    mix_kernel<<<dim3(NT, NB), 256>>>(w1, w2, s, ahi);
    // 8) O = attn @ V (pure fp16)
    mma_gemm<0,1><<<dim3(2, 32, NB), 256, 98304>>>(
        ahi, NT, (long)NT * NT, vThi, nullptr, (long)NB * NT, NT,
        o, nullptr, NC, (long)NT * NC, NT);
    // 9) transpose + residual
    out_kernel<<<dim3(NT / 32, NC / 32, NB), dim3(32, 8)>>>(o, xnhi, xnlo, out);
}

// round 13
// speedup vs baseline: 2.4574x; 1.0013x over previous
#include <cuda_runtime.h>
#include <cuda_fp16.h>
#include <math.h>
#include <stdint.h>

#define NB 4
#define NC 256
#define NT 4096

typedef __half h16;

__device__ h16   g_xnhi[NB * NT * NC];
__device__ h16   g_xnlo[NB * NT * NC];
__device__ h16   g_qhi [NB * NT * NC];
__device__ h16   g_khi [NB * NT * NC];
__device__ h16   g_vThi[NC * NB * NT];
__device__ float g_s   [(size_t)NB * NT * NT];
__device__ h16   g_ahi [(size_t)NB * NT * NT];
__device__ float g_o   [NB * NT * NC];
__device__ h16   g_wqhi[NC * NC], g_wqlo[NC * NC];
__device__ h16   g_wkhi[NC * NC], g_wklo[NC * NC];
__device__ h16   g_wvhi[NC * NC], g_wvlo[NC * NC];

__device__ __forceinline__ uint32_t smem_u32(const void* p) {
    uint32_t a;
    asm("{ .reg .u64 t; cvta.to.shared.u64 t, %1; cvt.u32.u64 %0, t; }" : "=r"(a) : "l"(p));
    return a;
}
__device__ __forceinline__ void cp16(uint32_t s, const void* g) {
    asm volatile("cp.async.cg.shared.global [%0], [%1], 16;" :: "r"(s), "l"(g));
}
__device__ __forceinline__ void cp_commit() { asm volatile("cp.async.commit_group;" ::: "memory"); }
template <int N> __device__ __forceinline__ void cp_wait() {
    asm volatile("cp.async.wait_group %0;" :: "n"(N) : "memory");
}
__device__ __forceinline__ void ldm_x4(uint32_t* r, uint32_t addr) {
    asm volatile("ldmatrix.sync.aligned.m8n8.x4.shared.b16 {%0,%1,%2,%3}, [%4];"
                 : "=r"(r[0]), "=r"(r[1]), "=r"(r[2]), "=r"(r[3]) : "r"(addr));
}
__device__ __forceinline__ void mma16816(float* d, const uint32_t* a, const uint32_t* b) {
    asm volatile(
        "mma.sync.aligned.m16n8k16.row.col.f32.f16.f16.f32 "
        "{%0,%1,%2,%3}, {%4,%5,%6,%7}, {%8,%9}, {%0,%1,%2,%3};"
        : "+f"(d[0]), "+f"(d[1]), "+f"(d[2]), "+f"(d[3])
        : "r"(a[0]), "r"(a[1]), "r"(a[2]), "r"(a[3]), "r"(b[0]), "r"(b[1]));
}
__device__ __forceinline__ uint32_t swz(uint32_t off) { return off ^ ((off >> 3) & 0x70); }
__device__ __forceinline__ uint32_t pack2h(float a, float b) {
    return (uint32_t)__half_as_ushort(__float2half_rn(a))
         | ((uint32_t)__half_as_ushort(__float2half_rn(b)) << 16);
}

// ============================================================
// split-fp16 GEMM, BK=64, clean 128B rows.
//   NPROD=1: Ahi*Bhi               3 stages x 32KB, reg-pingpong frags
//   NPROD=2: Ahi*Bhi + Ahi*Blo     2 stages x 48KB
// BM=BN=128, 256 thr (8 warps 2x4), warp tile 64x32, 2 CTA/SM.
// EPI=0: fp32 out. EPI=1: fp16 hi out.
// ============================================================
template <int EPI, int NPROD>
__global__ void __launch_bounds__(256, 2) mma_gemm(
    const h16* __restrict__ Ahi, long ldA, long strideA,
    const h16* __restrict__ Bhi, const h16* __restrict__ Blo, long ldB, long strideB,
    float* __restrict__ Cf, h16* __restrict__ Chi,
    long ldC, long strideC, int K)
{
    extern __shared__ char dyn[];
    const uint32_t sbase = smem_u32(dyn);
    const int tid = threadIdx.x;
    const int wid = tid >> 5, lane = tid & 31;
    const int warpM = wid & 1, warpN = wid >> 1;

    constexpr int NSTAGE = (NPROD == 1) ? 3 : 2;
    constexpr uint32_t PLANE = 16384;
    constexpr uint32_t STAGE = PLANE * (1 + NPROD);

    const int z = blockIdx.z;
    const long m0 = (long)blockIdx.y * 128;
    const long n0 = (long)blockIdx.x * 128;
    const h16* pAh = Ahi + (size_t)z * strideA + (size_t)m0 * ldA;
    const h16* pBh = Bhi + (size_t)z * strideB + (size_t)n0 * ldB;
    const h16* pBl = (NPROD >= 2) ? Blo + (size_t)z * strideB + (size_t)n0 * ldB : nullptr;

    const int nk = K / 64;

    auto load_stage = [&](int st, int ks) {
        uint32_t base = sbase + (uint32_t)st * STAGE;
#pragma unroll
        for (int i = 0; i < 4; i++) {
            int cid = tid + i * 256;
            int m = cid >> 3, c = cid & 7;
            uint32_t off = swz((uint32_t)(m * 128 + c * 16));
            cp16(base + off,          pAh + (size_t)m * ldA + ks * 64 + c * 8);
            cp16(base + PLANE + off,  pBh + (size_t)m * ldB + ks * 64 + c * 8);
            if (NPROD >= 2)
                cp16(base + 2 * PLANE + off, pBl + (size_t)m * ldB + ks * 64 + c * 8);
        }
    };

    const int lr = lane & 7, lg = lane >> 3;

    // fragment loaders (kst = 0..3 within a stage)
    auto load_afrag = [&](uint32_t aBase, int kst, uint32_t (*ah)[4]) {
        const uint32_t kb = (uint32_t)kst * 32;
#pragma unroll
        for (int mf = 0; mf < 4; mf++) {
            uint32_t row = warpM * 64 + mf * 16 + lr + ((lg & 1) << 3);
            ldm_x4(ah[mf], aBase + swz(row * 128 + kb + ((lg >> 1) << 4)));
        }
    };
    auto load_bfrag = [&](uint32_t bBase, int kst, uint32_t (*bh)[2]) {
        const uint32_t kb = (uint32_t)kst * 32;
#pragma unroll
        for (int p = 0; p < 2; p++) {
            uint32_t row = warpN * 32 + p * 16 + lr + ((lg >> 1) << 3);
            uint32_t t[4];
            ldm_x4(t, bBase + swz(row * 128 + kb + ((lg & 1) << 4)));
            bh[2*p][0] = t[0]; bh[2*p][1] = t[1];
            bh[2*p+1][0] = t[2]; bh[2*p+1][1] = t[3];
        }
    };

    float acc[4][4][4] = {};
    load_stage(0, 0); cp_commit();
    if (NSTAGE == 3 && nk > 1) { load_stage(1, 1); cp_commit(); }

    for (int ks = 0; ks < nk; ks++) {
        if (NSTAGE == 3) {
            if (ks + 1 < nk) cp_wait<1>(); else cp_wait<0>();
            __syncthreads();
            if (ks + 2 < nk) { load_stage((ks + 2) % 3, ks + 2); cp_commit(); }
        } else {
            cp_wait<0>();
            __syncthreads();
            if (ks + 1 < nk) { load_stage((ks + 1) & 1, ks + 1); cp_commit(); }
        }

        uint32_t aBase = sbase + (uint32_t)(ks % NSTAGE) * STAGE;
        uint32_t bBase = aBase + PLANE;

        if (NPROD == 1) {
            // register-pingpong: prefetch kst+1 fragments before kst's MMAs
            uint32_t ah[2][4][4], bh[2][4][2];
            load_afrag(aBase, 0, ah[0]);
            load_bfrag(bBase, 0, bh[0]);
#pragma unroll
            for (int kst = 0; kst < 4; kst++) {
                const int cur = kst & 1;
                if (kst < 3) {
                    load_afrag(aBase, kst + 1, ah[cur ^ 1]);
                    load_bfrag(bBase, kst + 1, bh[cur ^ 1]);
                }
#pragma unroll
                for (int mf = 0; mf < 4; mf++)
#pragma unroll
                    for (int nf = 0; nf < 4; nf++)
                        mma16816(acc[mf][nf], ah[cur][mf], bh[cur][nf]);
            }
        } else {
            uint32_t lBase = aBase + 2 * PLANE;
#pragma unroll
            for (int kst = 0; kst < 4; kst++) {
                uint32_t ah[4][4], bh[4][2];
                load_afrag(aBase, kst, ah);
                load_bfrag(bBase, kst, bh);
#pragma unroll
                for (int mf = 0; mf < 4; mf++)
#pragma unroll
                    for (int nf = 0; nf < 4; nf++)
                        mma16816(acc[mf][nf], ah[mf], bh[nf]);
                uint32_t bl[4][2];
                load_bfrag(lBase, kst, bl);
#pragma unroll
                for (int mf = 0; mf < 4; mf++)
#pragma unroll
                    for (int nf = 0; nf < 4; nf++)
                        mma16816(acc[mf][nf], ah[mf], bl[nf]);
            }
        }
    }

    const int qr = lane >> 2, qc = (lane & 3) * 2;
#pragma unroll
    for (int mf = 0; mf < 4; mf++) {
#pragma unroll
        for (int nf = 0; nf < 4; nf++) {
            long r0  = m0 + warpM * 64 + mf * 16 + qr;
            long col = n0 + warpN * 32 + nf * 8 + qc;
            if (EPI == 0) {
                float* d0 = Cf + (size_t)z * strideC + (size_t)r0 * ldC + col;
                *(float2*)d0             = make_float2(acc[mf][nf][0], acc[mf][nf][1]);
                *(float2*)(d0 + 8 * ldC) = make_float2(acc[mf][nf][2], acc[mf][nf][3]);
            } else {
#pragma unroll
                for (int h = 0; h < 2; h++) {
                    size_t idx = (size_t)z * strideC + (size_t)(r0 + h * 8) * ldC + col;
                    *(uint32_t*)(Chi + idx) = pack2h(acc[mf][nf][2*h], acc[mf][nf][2*h+1]);
                }
            }
        }
    }
}

// ============================================================
__global__ void __launch_bounds__(256) ln_kernel(
    const float* __restrict__ x, const float* __restrict__ gamma,
    const float* __restrict__ beta, h16* __restrict__ xnhi, h16* __restrict__ xnlo)
{
    __shared__ float sx[32][NC + 1];
    __shared__ float psum[8][33], psq[8][33];
    __shared__ float smu[32], srs[32];
    int b = blockIdx.y, n0 = blockIdx.x * 32;
    const float* xb = x + (size_t)b * NC * NT;

    for (int i = threadIdx.x; i < NC * 32; i += 256) {
        int c = i >> 5, t = i & 31;
        sx[t][c] = xb[(size_t)c * NT + n0 + t];
    }
    __syncthreads();
    int t = threadIdx.x & 31, g = threadIdx.x >> 5;
    float s0 = 0.f, s1 = 0.f;
#pragma unroll
    for (int j = 0; j < 32; j++) { float v = sx[t][g * 32 + j]; s0 += v; s1 += v * v; }
    psum[g][t] = s0; psq[g][t] = s1;
    __syncthreads();
    if (threadIdx.x < 32) {
        float a = 0.f, bb = 0.f;
#pragma unroll
        for (int j = 0; j < 8; j++) { a += psum[j][threadIdx.x]; bb += psq[j][threadIdx.x]; }
        float mu = a * (1.0f / NC);
        smu[threadIdx.x] = mu;
        srs[threadIdx.x] = rsqrtf(bb * (1.0f / NC) - mu * mu + 1e-5f);
    }
    __syncthreads();
    size_t base = ((size_t)b * NT + n0) * NC;
    for (int i = threadIdx.x; i < NC * 32; i += 256) {
        int tok = i >> 8, c = i & 255;
        float r = (sx[tok][c] - smu[tok]) * srs[tok] * gamma[c] + beta[c];
        float h = __half2float(__float2half_rn(r));
        xnhi[base + (size_t)tok * NC + c] = __float2half_rn(r);
        xnlo[base + (size_t)tok * NC + c] = __float2half_rn(r - h);
    }
}

__global__ void prep_kernel(
    const float* __restrict__ Wq, const float* __restrict__ Wk, const float* __restrict__ Wv,
    h16* qh, h16* ql, h16* kh, h16* kl, h16* vh, h16* vl)
{
    int n = blockIdx.x, k = threadIdx.x;
    size_t src = (size_t)k * NC + n, dst = (size_t)n * NC + k;
    float v, h;
    v = Wq[src]; h = __half2float(__float2half_rn(v)); qh[dst] = __float2half_rn(v); ql[dst] = __float2half_rn(v - h);
    v = Wk[src]; h = __half2float(__float2half_rn(v)); kh[dst] = __float2half_rn(v); kl[dst] = __float2half_rn(v - h);
    v = Wv[src]; h = __half2float(__float2half_rn(v)); vh[dst] = __float2half_rn(v); vl[dst] = __float2half_rn(v - h);
}

// mix: attn = a1*softmax + a2*relu^2, fp16 hi-only out
__global__ void __launch_bounds__(256) mix_kernel(
    const float* __restrict__ w1, const float* __restrict__ w2,
    const float* __restrict__ S, h16* __restrict__ ahi)
{
    size_t ro = ((size_t)blockIdx.y * NT + blockIdx.x) * NT;
    const float4* row4 = (const float4*)(S + ro);
    int tid = threadIdx.x;
    __shared__ float sred[8];

    float4 v[4];
    float mx = -1e30f;
#pragma unroll
    for (int g = 0; g < 4; g++) {
        v[g] = row4[g * 256 + tid];
        mx = fmaxf(mx, fmaxf(fmaxf(v[g].x, v[g].y), fmaxf(v[g].z, v[g].w)));
    }
#pragma unroll
    for (int o = 16; o; o >>= 1) mx = fmaxf(mx, __shfl_xor_sync(0xffffffffu, mx, o));
    if ((tid & 31) == 0) sred[tid >> 5] = mx;
    __syncthreads();
    mx = sred[0];
#pragma unroll
    for (int i = 1; i < 8; i++) mx = fmaxf(mx, sred[i]);
    __syncthreads();

    float4 e[4];
    float sum = 0.f;
#pragma unroll
    for (int g = 0; g < 4; g++) {
        e[g].x = __expf(v[g].x - mx); e[g].y = __expf(v[g].y - mx);
        e[g].z = __expf(v[g].z - mx); e[g].w = __expf(v[g].w - mx);
        sum += e[g].x + e[g].y + e[g].z + e[g].w;
    }
#pragma unroll
    for (int o = 16; o; o >>= 1) sum += __shfl_xor_sync(0xffffffffu, sum, o);
    if ((tid & 31) == 0) sred[tid >> 5] = sum;
    __syncthreads();
    sum = 0.f;
#pragma unroll
    for (int i = 0; i < 8; i++) sum += sred[i];

    float e1 = __expf(w1[0]), e2 = __expf(w2[0]);
    float a1 = e1 / (e1 + e2), a2 = e2 / (e1 + e2);
    float inv = a1 / sum;

    uint2* oh = (uint2*)(ahi + ro);
#pragma unroll
    for (int g = 0; g < 4; g++) {
        float p0 = e[g].x * inv + a2 * fmaxf(v[g].x, 0.f) * fmaxf(v[g].x, 0.f);
        float p1 = e[g].y * inv + a2 * fmaxf(v[g].y, 0.f) * fmaxf(v[g].y, 0.f);
        float p2 = e[g].z * inv + a2 * fmaxf(v[g].z, 0.f) * fmaxf(v[g].z, 0.f);
        float p3 = e[g].w * inv + a2 * fmaxf(v[g].w, 0.f) * fmaxf(v[g].w, 0.f);
        oh[g * 256 + tid] = make_uint2(pack2h(p0, p1), pack2h(p2, p3));
    }
}

__global__ void out_kernel(const float* __restrict__ o, const h16* __restrict__ xnhi,
                           const h16* __restrict__ xnlo, float* __restrict__ out)
{
    __shared__ float tile[32][33];
    int b = blockIdx.z, n0 = blockIdx.x * 32, c0 = blockIdx.y * 32;
    for (int r = threadIdx.y; r < 32; r += 8) {
        size_t idx = ((size_t)b * NT + n0 + r) * NC + c0 + threadIdx.x;
        tile[r][threadIdx.x] = o[idx] + __half2float(xnhi[idx]) + __half2float(xnlo[idx]);
    }
    __syncthreads();
    for (int r = threadIdx.y; r < 32; r += 8)
        out[((size_t)b * NC + c0 + r) * NT + n0 + threadIdx.x] = tile[threadIdx.x][r];
}

// ============================================================
extern "C" void kernel_launch(void* const* d_in, const int* in_sizes, int n_in,
                              void* d_out, int out_size)
{
    const float* x     = (const float*)d_in[0];
    const float* gamma = (const float*)d_in[1];
    const float* beta  = (const float*)d_in[2];
    const float* Wq    = (const float*)d_in[3];
    const float* Wk    = (const float*)d_in[4];
    const float* Wv    = (const float*)d_in[5];
    const float* w1    = (const float*)d_in[6];
    const float* w2    = (const float*)d_in[7];
    float* out = (float*)d_out;

    h16 *xnhi, *xnlo, *qhi, *khi, *vThi;
    h16 *wqhi, *wqlo, *wkhi, *wklo, *wvhi, *wvlo, *ahi;
    float *s, *o;
    cudaGetSymbolAddress((void**)&xnhi, g_xnhi); cudaGetSymbolAddress((void**)&xnlo, g_xnlo);
    cudaGetSymbolAddress((void**)&qhi,  g_qhi);
    cudaGetSymbolAddress((void**)&khi,  g_khi);
    cudaGetSymbolAddress((void**)&vThi, g_vThi);
    cudaGetSymbolAddress((void**)&wqhi, g_wqhi); cudaGetSymbolAddress((void**)&wqlo, g_wqlo);
    cudaGetSymbolAddress((void**)&wkhi, g_wkhi); cudaGetSymbolAddress((void**)&wklo, g_wklo);
    cudaGetSymbolAddress((void**)&wvhi, g_wvhi); cudaGetSymbolAddress((void**)&wvlo, g_wvlo);
    cudaGetSymbolAddress((void**)&ahi,  g_ahi);
    cudaGetSymbolAddress((void**)&s, g_s); cudaGetSymbolAddress((void**)&o, g_o);

    cudaFuncSetAttribute((const void*)mma_gemm<1,2>, cudaFuncAttributeMaxDynamicSharedMemorySize, 98304);
    cudaFuncSetAttribute((const void*)mma_gemm<0,1>, cudaFuncAttributeMaxDynamicSharedMemorySize, 98304);

    // 1) LayerNorm -> xn pair
    ln_kernel<<<dim3(NT / 32, NB), 256>>>(x, gamma, beta, xnhi, xnlo);
    // 2) weight transpose+split
    prep_kernel<<<NC, NC>>>(Wq, Wk, Wv, wqhi, wqlo, wkhi, wklo, wvhi, wvlo);
    // 3-5) Q, K, V^T projections (2-product: xn_hi x W-pair, hi out)
    mma_gemm<1,2><<<dim3(2, 128, 1), 256, 98304>>>(
        xnhi, NC, 0, wqhi, wqlo, NC, 0, nullptr, qhi, NC, 0, NC);
    mma_gemm<1,2><<<dim3(2, 128, 1), 256, 98304>>>(
        xnhi, NC, 0, wkhi, wklo, NC, 0, nullptr, khi, NC, 0, NC);
    mma_gemm<1,2><<<dim3(128, 2, 1), 256, 98304>>>(
        wvhi, NC, 0, xnhi, xnlo, NC, 0, nullptr, vThi, (long)NB * NT, 0, NC);
    // 6) S = Q K^T (pure fp16, reg-pingpong)  <- ncu 6th launch
    mma_gemm<0,1><<<dim3(32, 32, NB), 256, 98304>>>(
        qhi, NC, (long)NT * NC, khi, nullptr, NC, (long)NT * NC,
        s, nullptr, NT, (long)NT * NT, NC);
    // 7) attn mix -> fp16 hi only
    mix_kernel<<<dim3(NT, NB), 256>>>(w1, w2, s, ahi);
    // 8) O = attn @ V (pure fp16, reg-pingpong)
    mma_gemm<0,1><<<dim3(2, 32, NB), 256, 98304>>>(
        ahi, NT, (long)NT * NT, vThi, nullptr, (long)NB * NT, NT,
        o, nullptr, NC, (long)NT * NC, NT);
    // 9) transpose + residual
    out_kernel<<<dim3(NT / 32, NC / 32, NB), dim3(32, 8)>>>(o, xnhi, xnlo, out);
}

// round 14
// speedup vs baseline: 2.5764x; 1.0484x over previous
#include <cuda_runtime.h>
#include <cuda_fp16.h>
#include <math.h>
#include <stdint.h>

#define NB 4
#define NC 256
#define NT 4096

typedef __half h16;

__device__ h16   g_xnhi[NB * NT * NC];
__device__ h16   g_xnlo[NB * NT * NC];
__device__ h16   g_qhi [NB * NT * NC];
__device__ h16   g_khi [NB * NT * NC];
__device__ h16   g_vThi[NC * NB * NT];
__device__ h16   g_s16 [(size_t)NB * NT * NT];
__device__ h16   g_ahi [(size_t)NB * NT * NT];
__device__ h16   g_wqhi[NC * NC], g_wqlo[NC * NC];
__device__ h16   g_wkhi[NC * NC], g_wklo[NC * NC];
__device__ h16   g_wvhi[NC * NC], g_wvlo[NC * NC];

__device__ __forceinline__ uint32_t smem_u32(const void* p) {
    uint32_t a;
    asm("{ .reg .u64 t; cvta.to.shared.u64 t, %1; cvt.u32.u64 %0, t; }" : "=r"(a) : "l"(p));
    return a;
}
__device__ __forceinline__ void cp16(uint32_t s, const void* g) {
    asm volatile("cp.async.cg.shared.global [%0], [%1], 16;" :: "r"(s), "l"(g));
}
__device__ __forceinline__ void cp_commit() { asm volatile("cp.async.commit_group;" ::: "memory"); }
template <int N> __device__ __forceinline__ void cp_wait() {
    asm volatile("cp.async.wait_group %0;" :: "n"(N) : "memory");
}
__device__ __forceinline__ void ldm_x4(uint32_t* r, uint32_t addr) {
    asm volatile("ldmatrix.sync.aligned.m8n8.x4.shared.b16 {%0,%1,%2,%3}, [%4];"
                 : "=r"(r[0]), "=r"(r[1]), "=r"(r[2]), "=r"(r[3]) : "r"(addr));
}
__device__ __forceinline__ void mma16816(float* d, const uint32_t* a, const uint32_t* b) {
    asm volatile(
        "mma.sync.aligned.m16n8k16.row.col.f32.f16.f16.f32 "
        "{%0,%1,%2,%3}, {%4,%5,%6,%7}, {%8,%9}, {%0,%1,%2,%3};"
        : "+f"(d[0]), "+f"(d[1]), "+f"(d[2]), "+f"(d[3])
        : "r"(a[0]), "r"(a[1]), "r"(a[2]), "r"(a[3]), "r"(b[0]), "r"(b[1]));
}
__device__ __forceinline__ uint32_t swz(uint32_t off) { return off ^ ((off >> 3) & 0x70); }
__device__ __forceinline__ uint32_t pack2h(float a, float b) {
    return (uint32_t)__half_as_ushort(__float2half_rn(a))
         | ((uint32_t)__half_as_ushort(__float2half_rn(b)) << 16);
}

// ============================================================
// split-fp16 GEMM, BK=64, clean 128B rows.
//   NPROD=1: Ahi*Bhi               3 stages x 32KB
//   NPROD=2: Ahi*Bhi + Ahi*Blo     2 stages x 48KB
// BM=BN=128, 256 thr (8 warps 2x4), warp tile 64x32, 2 CTA/SM.
// EPI=1: fp16 out. EPI=2: += residual(Rhi+Rlo at [row,col]),
//        transpose via smem, write fp32 out[b,c,n] (O-GEMM only).
// ============================================================
template <int EPI, int NPROD>
__global__ void __launch_bounds__(256, 2) mma_gemm(
    const h16* __restrict__ Ahi, long ldA, long strideA,
    const h16* __restrict__ Bhi, const h16* __restrict__ Blo, long ldB, long strideB,
    float* __restrict__ Cf, h16* __restrict__ Chi,
    long ldC, long strideC, int K,
    const h16* __restrict__ Rhi, const h16* __restrict__ Rlo)
{
    extern __shared__ char dyn[];
    const uint32_t sbase = smem_u32(dyn);
    const int tid = threadIdx.x;
    const int wid = tid >> 5, lane = tid & 31;
    const int warpM = wid & 1, warpN = wid >> 1;

    constexpr int NSTAGE = (NPROD == 1) ? 3 : 2;
    constexpr uint32_t PLANE = 16384;
    constexpr uint32_t STAGE = PLANE * (1 + NPROD);

    const int z = blockIdx.z;
    const long m0 = (long)blockIdx.y * 128;
    const long n0 = (long)blockIdx.x * 128;
    const h16* pAh = Ahi + (size_t)z * strideA + (size_t)m0 * ldA;
    const h16* pBh = Bhi + (size_t)z * strideB + (size_t)n0 * ldB;
    const h16* pBl = (NPROD >= 2) ? Blo + (size_t)z * strideB + (size_t)n0 * ldB : nullptr;

    const int nk = K / 64;

    auto load_stage = [&](int st, int ks) {
        uint32_t base = sbase + (uint32_t)st * STAGE;
#pragma unroll
        for (int i = 0; i < 4; i++) {
            int cid = tid + i * 256;
            int m = cid >> 3, c = cid & 7;
            uint32_t off = swz((uint32_t)(m * 128 + c * 16));
            cp16(base + off,          pAh + (size_t)m * ldA + ks * 64 + c * 8);
            cp16(base + PLANE + off,  pBh + (size_t)m * ldB + ks * 64 + c * 8);
            if (NPROD >= 2)
                cp16(base + 2 * PLANE + off, pBl + (size_t)m * ldB + ks * 64 + c * 8);
        }
    };

    const int lr = lane & 7, lg = lane >> 3;

    auto load_afrag = [&](uint32_t aBase, int kst, uint32_t (*ah)[4]) {
        const uint32_t kb = (uint32_t)kst * 32;
#pragma unroll
        for (int mf = 0; mf < 4; mf++) {
            uint32_t row = warpM * 64 + mf * 16 + lr + ((lg & 1) << 3);
            ldm_x4(ah[mf], aBase + swz(row * 128 + kb + ((lg >> 1) << 4)));
        }
    };
    auto load_bfrag = [&](uint32_t bBase, int kst, uint32_t (*bh)[2]) {
        const uint32_t kb = (uint32_t)kst * 32;
#pragma unroll
        for (int p = 0; p < 2; p++) {
            uint32_t row = warpN * 32 + p * 16 + lr + ((lg >> 1) << 3);
            uint32_t t[4];
            ldm_x4(t, bBase + swz(row * 128 + kb + ((lg & 1) << 4)));
            bh[2*p][0] = t[0]; bh[2*p][1] = t[1];
            bh[2*p+1][0] = t[2]; bh[2*p+1][1] = t[3];
        }
    };

    float acc[4][4][4] = {};
    load_stage(0, 0); cp_commit();
    if (NSTAGE == 3 && nk > 1) { load_stage(1, 1); cp_commit(); }

    for (int ks = 0; ks < nk; ks++) {
        if (NSTAGE == 3) {
            if (ks + 1 < nk) cp_wait<1>(); else cp_wait<0>();
            __syncthreads();
            if (ks + 2 < nk) { load_stage((ks + 2) % 3, ks + 2); cp_commit(); }
        } else {
            cp_wait<0>();
            __syncthreads();
            if (ks + 1 < nk) { load_stage((ks + 1) & 1, ks + 1); cp_commit(); }
        }

        uint32_t aBase = sbase + (uint32_t)(ks % NSTAGE) * STAGE;
        uint32_t bBase = aBase + PLANE;

#pragma unroll
        for (int kst = 0; kst < 4; kst++) {
            uint32_t ah[4][4], bh[4][2];
            load_afrag(aBase, kst, ah);
            load_bfrag(bBase, kst, bh);
#pragma unroll
            for (int mf = 0; mf < 4; mf++)
#pragma unroll
                for (int nf = 0; nf < 4; nf++)
                    mma16816(acc[mf][nf], ah[mf], bh[nf]);
            if (NPROD >= 2) {
                uint32_t bl[4][2];
                load_bfrag(aBase + 2 * PLANE, kst, bl);
#pragma unroll
                for (int mf = 0; mf < 4; mf++)
#pragma unroll
                    for (int nf = 0; nf < 4; nf++)
                        mma16816(acc[mf][nf], ah[mf], bl[nf]);
            }
        }
    }

    const int qr = lane >> 2, qc = (lane & 3) * 2;

    if (EPI == 1) {
#pragma unroll
        for (int mf = 0; mf < 4; mf++)
#pragma unroll
            for (int nf = 0; nf < 4; nf++) {
                long r0  = m0 + warpM * 64 + mf * 16 + qr;
                long col = n0 + warpN * 32 + nf * 8 + qc;
#pragma unroll
                for (int h = 0; h < 2; h++) {
                    size_t idx = (size_t)z * strideC + (size_t)(r0 + h * 8) * ldC + col;
                    *(uint32_t*)(Chi + idx) = pack2h(acc[mf][nf][2*h], acc[mf][nf][2*h+1]);
                }
            }
    } else {
        // EPI == 2: residual add + transpose + coalesced out[b,c,n]
        __syncthreads();                       // done reading pipeline smem
        float* tr = (float*)dyn;               // [128][132]
#pragma unroll
        for (int mf = 0; mf < 4; mf++)
#pragma unroll
            for (int nf = 0; nf < 4; nf++) {
                int row_l = warpM * 64 + mf * 16 + qr;
                int col_l = warpN * 32 + nf * 8 + qc;
#pragma unroll
                for (int h = 0; h < 2; h++) {
                    size_t idx = ((size_t)z * NT + m0 + row_l + h * 8) * NC + n0 + col_l;
                    uint32_t xh = *(const uint32_t*)(Rhi + idx);
                    uint32_t xl = *(const uint32_t*)(Rlo + idx);
                    float r0v = __half2float(__ushort_as_half((unsigned short)(xh & 0xffff)))
                              + __half2float(__ushort_as_half((unsigned short)(xl & 0xffff)));
                    float r1v = __half2float(__ushort_as_half((unsigned short)(xh >> 16)))
                              + __half2float(__ushort_as_half((unsigned short)(xl >> 16)));
                    tr[(col_l)     * 132 + row_l + h * 8] = acc[mf][nf][2*h]     + r0v;
                    tr[(col_l + 1) * 132 + row_l + h * 8] = acc[mf][nf][2*h + 1] + r1v;
                }
            }
        __syncthreads();
#pragma unroll
        for (int it = 0; it < 16; it++) {
            int col = (tid >> 5) + it * 8;
            int t4  = lane * 4;
            float4 v = *(float4*)&tr[col * 132 + t4];
            *(float4*)(Cf + ((size_t)z * NC + n0 + col) * NT + m0 + t4) = v;
        }
    }
}

// ============================================================
__global__ void __launch_bounds__(256) ln_kernel(
    const float* __restrict__ x, const float* __restrict__ gamma,
    const float* __restrict__ beta, h16* __restrict__ xnhi, h16* __restrict__ xnlo)
{
    __shared__ float sx[32][NC + 1];
    __shared__ float psum[8][33], psq[8][33];
    __shared__ float smu[32], srs[32];
    int b = blockIdx.y, n0 = blockIdx.x * 32;
    const float* xb = x + (size_t)b * NC * NT;

    for (int i = threadIdx.x; i < NC * 32; i += 256) {
        int c = i >> 5, t = i & 31;
        sx[t][c] = xb[(size_t)c * NT + n0 + t];
    }
    __syncthreads();
    int t = threadIdx.x & 31, g = threadIdx.x >> 5;
    float s0 = 0.f, s1 = 0.f;
#pragma unroll
    for (int j = 0; j < 32; j++) { float v = sx[t][g * 32 + j]; s0 += v; s1 += v * v; }
    psum[g][t] = s0; psq[g][t] = s1;
    __syncthreads();
    if (threadIdx.x < 32) {
        float a = 0.f, bb = 0.f;
#pragma unroll
        for (int j = 0; j < 8; j++) { a += psum[j][threadIdx.x]; bb += psq[j][threadIdx.x]; }
        float mu = a * (1.0f / NC);
        smu[threadIdx.x] = mu;
        srs[threadIdx.x] = rsqrtf(bb * (1.0f / NC) - mu * mu + 1e-5f);
    }
    __syncthreads();
    size_t base = ((size_t)b * NT + n0) * NC;
    for (int i = threadIdx.x; i < NC * 32; i += 256) {
        int tok = i >> 8, c = i & 255;
        float r = (sx[tok][c] - smu[tok]) * srs[tok] * gamma[c] + beta[c];
        float h = __half2float(__float2half_rn(r));
        xnhi[base + (size_t)tok * NC + c] = __float2half_rn(r);
        xnlo[base + (size_t)tok * NC + c] = __float2half_rn(r - h);
    }
}

__global__ void prep_kernel(
    const float* __restrict__ Wq, const float* __restrict__ Wk, const float* __restrict__ Wv,
    h16* qh, h16* ql, h16* kh, h16* kl, h16* vh, h16* vl)
{
    int n = blockIdx.x, k = threadIdx.x;
    size_t src = (size_t)k * NC + n, dst = (size_t)n * NC + k;
    float v, h;
    v = Wq[src]; h = __half2float(__float2half_rn(v)); qh[dst] = __float2half_rn(v); ql[dst] = __float2half_rn(v - h);
    v = Wk[src]; h = __half2float(__float2half_rn(v)); kh[dst] = __float2half_rn(v); kl[dst] = __float2half_rn(v - h);
    v = Wv[src]; h = __half2float(__float2half_rn(v)); vh[dst] = __float2half_rn(v); vl[dst] = __float2half_rn(v - h);
}

// mix: attn = a1*softmax + a2*relu^2, fp16 in/out
__global__ void __launch_bounds__(256) mix_kernel(
    const float* __restrict__ w1, const float* __restrict__ w2,
    const h16* __restrict__ S, h16* __restrict__ ahi)
{
    size_t ro = ((size_t)blockIdx.y * NT + blockIdx.x) * NT;
    const uint2* row2 = (const uint2*)(S + ro);   // 4 halfs per uint2
    int tid = threadIdx.x;
    __shared__ float sred[8];

    float v[16];
    float mx = -1e30f;
#pragma unroll
    for (int g = 0; g < 4; g++) {
        uint2 u = row2[g * 256 + tid];
        v[g*4+0] = __half2float(__ushort_as_half((unsigned short)(u.x & 0xffff)));
        v[g*4+1] = __half2float(__ushort_as_half((unsigned short)(u.x >> 16)));
        v[g*4+2] = __half2float(__ushort_as_half((unsigned short)(u.y & 0xffff)));
        v[g*4+3] = __half2float(__ushort_as_half((unsigned short)(u.y >> 16)));
    }
#pragma unroll
    for (int i = 0; i < 16; i++) mx = fmaxf(mx, v[i]);
#pragma unroll
    for (int o = 16; o; o >>= 1) mx = fmaxf(mx, __shfl_xor_sync(0xffffffffu, mx, o));
    if ((tid & 31) == 0) sred[tid >> 5] = mx;
    __syncthreads();
    mx = sred[0];
#pragma unroll
    for (int i = 1; i < 8; i++) mx = fmaxf(mx, sred[i]);
    __syncthreads();

    float e[16];
    float sum = 0.f;
#pragma unroll
    for (int i = 0; i < 16; i++) { e[i] = __expf(v[i] - mx); sum += e[i]; }
#pragma unroll
    for (int o = 16; o; o >>= 1) sum += __shfl_xor_sync(0xffffffffu, sum, o);
    if ((tid & 31) == 0) sred[tid >> 5] = sum;
    __syncthreads();
    sum = 0.f;
#pragma unroll
    for (int i = 0; i < 8; i++) sum += sred[i];

    float e1 = __expf(w1[0]), e2 = __expf(w2[0]);
    float a1 = e1 / (e1 + e2), a2 = e2 / (e1 + e2);
    float inv = a1 / sum;

    uint2* oh = (uint2*)(ahi + ro);
#pragma unroll
    for (int g = 0; g < 4; g++) {
        float p[4];
#pragma unroll
        for (int j = 0; j < 4; j++) {
            float r = fmaxf(v[g*4+j], 0.f);
            p[j] = e[g*4+j] * inv + a2 * r * r;
        }
        oh[g * 256 + tid] = make_uint2(pack2h(p[0], p[1]), pack2h(p[2], p[3]));
    }
}

// ============================================================
extern "C" void kernel_launch(void* const* d_in, const int* in_sizes, int n_in,
                              void* d_out, int out_size)
{
    const float* x     = (const float*)d_in[0];
    const float* gamma = (const float*)d_in[1];
    const float* beta  = (const float*)d_in[2];
    const float* Wq    = (const float*)d_in[3];
    const float* Wk    = (const float*)d_in[4];
    const float* Wv    = (const float*)d_in[5];
    const float* w1    = (const float*)d_in[6];
    const float* w2    = (const float*)d_in[7];
    float* out = (float*)d_out;

    h16 *xnhi, *xnlo, *qhi, *khi, *vThi;
    h16 *wqhi, *wqlo, *wkhi, *wklo, *wvhi, *wvlo, *ahi, *s16;
    cudaGetSymbolAddress((void**)&xnhi, g_xnhi); cudaGetSymbolAddress((void**)&xnlo, g_xnlo);
    cudaGetSymbolAddress((void**)&qhi,  g_qhi);
    cudaGetSymbolAddress((void**)&khi,  g_khi);
    cudaGetSymbolAddress((void**)&vThi, g_vThi);
    cudaGetSymbolAddress((void**)&wqhi, g_wqhi); cudaGetSymbolAddress((void**)&wqlo, g_wqlo);
    cudaGetSymbolAddress((void**)&wkhi, g_wkhi); cudaGetSymbolAddress((void**)&wklo, g_wklo);
    cudaGetSymbolAddress((void**)&wvhi, g_wvhi); cudaGetSymbolAddress((void**)&wvlo, g_wvlo);
    cudaGetSymbolAddress((void**)&ahi,  g_ahi);  cudaGetSymbolAddress((void**)&s16,  g_s16);

    cudaFuncSetAttribute((const void*)mma_gemm<1,2>, cudaFuncAttributeMaxDynamicSharedMemorySize, 98304);
    cudaFuncSetAttribute((const void*)mma_gemm<1,1>, cudaFuncAttributeMaxDynamicSharedMemorySize, 98304);
    cudaFuncSetAttribute((const void*)mma_gemm<2,1>, cudaFuncAttributeMaxDynamicSharedMemorySize, 98304);

    // 1) LayerNorm -> xn pair
    ln_kernel<<<dim3(NT / 32, NB), 256>>>(x, gamma, beta, xnhi, xnlo);
    // 2) weight transpose+split
    prep_kernel<<<NC, NC>>>(Wq, Wk, Wv, wqhi, wqlo, wkhi, wklo, wvhi, wvlo);
    // 3-5) Q, K, V^T projections (2-product)
    mma_gemm<1,2><<<dim3(2, 128, 1), 256, 98304>>>(
        xnhi, NC, 0, wqhi, wqlo, NC, 0, nullptr, qhi, NC, 0, NC, nullptr, nullptr);
    mma_gemm<1,2><<<dim3(2, 128, 1), 256, 98304>>>(
        xnhi, NC, 0, wkhi, wklo, NC, 0, nullptr, khi, NC, 0, NC, nullptr, nullptr);
    mma_gemm<1,2><<<dim3(128, 2, 1), 256, 98304>>>(
        wvhi, NC, 0, xnhi, xnlo, NC, 0, nullptr, vThi, (long)NB * NT, 0, NC, nullptr, nullptr);
    // 6) S = Q K^T (pure fp16, fp16 out)  <- ncu 6th launch
    mma_gemm<1,1><<<dim3(32, 32, NB), 256, 98304>>>(
        qhi, NC, (long)NT * NC, khi, nullptr, NC, (long)NT * NC,
        nullptr, s16, NT, (long)NT * NT, NC, nullptr, nullptr);
    // 7) attn mix (fp16 in/out)
    mix_kernel<<<dim3(NT, NB), 256>>>(w1, w2, s16, ahi);
    // 8) O = attn @ V + residual + transpose -> out[b,c,n]
    mma_gemm<2,1><<<dim3(2, 32, NB), 256, 98304>>>(
        ahi, NT, (long)NT * NT, vThi, nullptr, (long)NB * NT, NT,
        out, nullptr, 0, 0, NT, xnhi, xnlo);
}

// round 15
// speedup vs baseline: 2.6501x; 1.0286x over previous
#include <cuda_runtime.h>
#include <cuda_fp16.h>
#include <math.h>
#include <stdint.h>

#define NB 4
#define NC 256
#define NT 4096

typedef __half h16;

__device__ h16   g_xnhi[NB * NT * NC];
__device__ h16   g_xnlo[NB * NT * NC];
__device__ h16   g_qhi [NB * NT * NC];
__device__ h16   g_khi [NB * NT * NC];
__device__ h16   g_vThi[NC * NB * NT];
__device__ h16   g_s16 [(size_t)NB * NT * NT];
__device__ h16   g_ahi [(size_t)NB * NT * NT];
__device__ h16   g_wqhi[NC * NC];
__device__ h16   g_wkhi[NC * NC];
__device__ h16   g_wvhi[NC * NC];

__device__ __forceinline__ uint32_t smem_u32(const void* p) {
    uint32_t a;
    asm("{ .reg .u64 t; cvta.to.shared.u64 t, %1; cvt.u32.u64 %0, t; }" : "=r"(a) : "l"(p));
    return a;
}
__device__ __forceinline__ void cp16(uint32_t s, const void* g) {
    asm volatile("cp.async.cg.shared.global [%0], [%1], 16;" :: "r"(s), "l"(g));
}
__device__ __forceinline__ void cp_commit() { asm volatile("cp.async.commit_group;" ::: "memory"); }
template <int N> __device__ __forceinline__ void cp_wait() {
    asm volatile("cp.async.wait_group %0;" :: "n"(N) : "memory");
}
__device__ __forceinline__ void ldm_x4(uint32_t* r, uint32_t addr) {
    asm volatile("ldmatrix.sync.aligned.m8n8.x4.shared.b16 {%0,%1,%2,%3}, [%4];"
                 : "=r"(r[0]), "=r"(r[1]), "=r"(r[2]), "=r"(r[3]) : "r"(addr));
}
__device__ __forceinline__ void mma16816(float* d, const uint32_t* a, const uint32_t* b) {
    asm volatile(
        "mma.sync.aligned.m16n8k16.row.col.f32.f16.f16.f32 "
        "{%0,%1,%2,%3}, {%4,%5,%6,%7}, {%8,%9}, {%0,%1,%2,%3};"
        : "+f"(d[0]), "+f"(d[1]), "+f"(d[2]), "+f"(d[3])
        : "r"(a[0]), "r"(a[1]), "r"(a[2]), "r"(a[3]), "r"(b[0]), "r"(b[1]));
}
__device__ __forceinline__ uint32_t swz(uint32_t off) { return off ^ ((off >> 3) & 0x70); }
__device__ __forceinline__ uint32_t pack2h(float a, float b) {
    return (uint32_t)__half_as_ushort(__float2half_rn(a))
         | ((uint32_t)__half_as_ushort(__float2half_rn(b)) << 16);
}

// ============================================================
// pure-fp16 GEMM (1 product), BK=64, BM=BN=128, 3 stages x 32KB.
// 256 thr (8 warps 2x4), warp tile 64x32, 2 CTA/SM, fp16 out.
// ============================================================
__global__ void __launch_bounds__(256, 2) mma_gemm(
    const h16* __restrict__ A, long ldA, long strideA,
    const h16* __restrict__ B, long ldB, long strideB,
    h16* __restrict__ C, long ldC, long strideC, int K)
{
    extern __shared__ char dyn[];
    const uint32_t sbase = smem_u32(dyn);
    const int tid = threadIdx.x;
    const int wid = tid >> 5, lane = tid & 31;
    const int warpM = wid & 1, warpN = wid >> 1;

    constexpr uint32_t PLANE = 16384, STAGE = 32768;

    const int z = blockIdx.z;
    const long m0 = (long)blockIdx.y * 128;
    const long n0 = (long)blockIdx.x * 128;
    const h16* pA = A + (size_t)z * strideA + (size_t)m0 * ldA;
    const h16* pB = B + (size_t)z * strideB + (size_t)n0 * ldB;

    const int nk = K / 64;

    auto load_stage = [&](int st, int ks) {
        uint32_t base = sbase + (uint32_t)st * STAGE;
#pragma unroll
        for (int i = 0; i < 4; i++) {
            int cid = tid + i * 256;
            int m = cid >> 3, c = cid & 7;
            uint32_t off = swz((uint32_t)(m * 128 + c * 16));
            cp16(base + off,         pA + (size_t)m * ldA + ks * 64 + c * 8);
            cp16(base + PLANE + off, pB + (size_t)m * ldB + ks * 64 + c * 8);
        }
    };

    const int lr = lane & 7, lg = lane >> 3;
    float acc[4][4][4] = {};
    load_stage(0, 0); cp_commit();
    if (nk > 1) { load_stage(1, 1); cp_commit(); }

    for (int ks = 0; ks < nk; ks++) {
        if (ks + 1 < nk) cp_wait<1>(); else cp_wait<0>();
        __syncthreads();
        if (ks + 2 < nk) { load_stage((ks + 2) % 3, ks + 2); cp_commit(); }

        uint32_t aBase = sbase + (uint32_t)(ks % 3) * STAGE;
        uint32_t bBase = aBase + PLANE;

#pragma unroll
        for (int kst = 0; kst < 4; kst++) {
            const uint32_t kb = kst * 32;
            uint32_t ah[4][4], bh[4][2];
#pragma unroll
            for (int mf = 0; mf < 4; mf++) {
                uint32_t row = warpM * 64 + mf * 16 + lr + ((lg & 1) << 3);
                ldm_x4(ah[mf], aBase + swz(row * 128 + kb + ((lg >> 1) << 4)));
            }
#pragma unroll
            for (int p = 0; p < 2; p++) {
                uint32_t row = warpN * 32 + p * 16 + lr + ((lg >> 1) << 3);
                uint32_t t[4];
                ldm_x4(t, bBase + swz(row * 128 + kb + ((lg & 1) << 4)));
                bh[2*p][0] = t[0]; bh[2*p][1] = t[1];
                bh[2*p+1][0] = t[2]; bh[2*p+1][1] = t[3];
            }
#pragma unroll
            for (int mf = 0; mf < 4; mf++)
#pragma unroll
                for (int nf = 0; nf < 4; nf++)
                    mma16816(acc[mf][nf], ah[mf], bh[nf]);
        }
    }

    const int qr = lane >> 2, qc = (lane & 3) * 2;
#pragma unroll
    for (int mf = 0; mf < 4; mf++)
#pragma unroll
        for (int nf = 0; nf < 4; nf++) {
            long r0  = m0 + warpM * 64 + mf * 16 + qr;
            long col = n0 + warpN * 32 + nf * 8 + qc;
#pragma unroll
            for (int h = 0; h < 2; h++) {
                size_t idx = (size_t)z * strideC + (size_t)(r0 + h * 8) * ldC + col;
                *(uint32_t*)(C + idx) = pack2h(acc[mf][nf][2*h], acc[mf][nf][2*h+1]);
            }
        }
}

// ============================================================
// O-GEMM: BM=64, BN=256 (full C), BK=64, 2 stages x 40KB.
// out[b,c,n] = (attn @ V)[n,c] + xn[n,c]  (residual + transpose).
// 256 thr, warp tile 32x64, 2 CTA/SM.
// ============================================================
__global__ void __launch_bounds__(256, 2) mma_o_gemm(
    const h16* __restrict__ A, const h16* __restrict__ Bv,
    const h16* __restrict__ Rhi, const h16* __restrict__ Rlo,
    float* __restrict__ out)
{
    extern __shared__ char dyn[];
    const uint32_t sbase = smem_u32(dyn);
    const int tid = threadIdx.x;
    const int wid = tid >> 5, lane = tid & 31;
    const int warpM = wid & 1, warpN = wid >> 1;

    constexpr uint32_t APLANE = 8192;           // 64 rows x 128B
    constexpr uint32_t STAGE  = 8192 + 32768;   // A + B(256x128B)

    const int z = blockIdx.z;
    const long m0 = (long)blockIdx.y * 64;
    const h16* pA = A + (size_t)z * NT * NT + (size_t)m0 * NT;
    const h16* pB = Bv + (size_t)z * NT;        // vT: [256 rows, ld NB*NT]

    const int nk = NT / 64;                     // 64

    auto load_stage = [&](int st, int ks) {
        uint32_t base = sbase + (uint32_t)st * STAGE;
#pragma unroll
        for (int i = 0; i < 10; i++) {
            int cid = tid + i * 256;            // 0..2559
            if (cid < 512) {
                int m = cid >> 3, c = cid & 7;
                uint32_t off = swz((uint32_t)(m * 128 + c * 16));
                cp16(base + off, pA + (size_t)m * NT + ks * 64 + c * 8);
            } else {
                int b = cid - 512;
                int m = b >> 3, c = b & 7;
                uint32_t off = swz((uint32_t)(m * 128 + c * 16));
                cp16(base + APLANE + off, pB + (size_t)m * (NB * NT) + ks * 64 + c * 8);
            }
        }
    };

    const int lr = lane & 7, lg = lane >> 3;
    float acc[2][8][4] = {};
    load_stage(0, 0); cp_commit();

    for (int ks = 0; ks < nk; ks++) {
        cp_wait<0>();
        __syncthreads();
        if (ks + 1 < nk) { load_stage((ks + 1) & 1, ks + 1); cp_commit(); }

        uint32_t aBase = sbase + (uint32_t)(ks & 1) * STAGE;
        uint32_t bBase = aBase + APLANE;

#pragma unroll
        for (int kst = 0; kst < 4; kst++) {
            const uint32_t kb = kst * 32;
            uint32_t ah[2][4], bh[8][2];
#pragma unroll
            for (int mf = 0; mf < 2; mf++) {
                uint32_t row = warpM * 32 + mf * 16 + lr + ((lg & 1) << 3);
                ldm_x4(ah[mf], aBase + swz(row * 128 + kb + ((lg >> 1) << 4)));
            }
#pragma unroll
            for (int p = 0; p < 4; p++) {
                uint32_t row = warpN * 64 + p * 16 + lr + ((lg >> 1) << 3);
                uint32_t t[4];
                ldm_x4(t, bBase + swz(row * 128 + kb + ((lg & 1) << 4)));
                bh[2*p][0] = t[0]; bh[2*p][1] = t[1];
                bh[2*p+1][0] = t[2]; bh[2*p+1][1] = t[3];
            }
#pragma unroll
            for (int mf = 0; mf < 2; mf++)
#pragma unroll
                for (int nf = 0; nf < 8; nf++)
                    mma16816(acc[mf][nf], ah[mf], bh[nf]);
        }
    }

    // epilogue: residual + transpose -> out[b, c, m0+row]
    const int qr = lane >> 2, qc = (lane & 3) * 2;
    __syncthreads();
    float* tr = (float*)dyn;                    // [256 cols][68]
#pragma unroll
    for (int mf = 0; mf < 2; mf++)
#pragma unroll
        for (int nf = 0; nf < 8; nf++) {
            int row_l = warpM * 32 + mf * 16 + qr;
            int col_l = warpN * 64 + nf * 8 + qc;
#pragma unroll
            for (int h = 0; h < 2; h++) {
                size_t idx = ((size_t)z * NT + m0 + row_l + h * 8) * NC + col_l;
                uint32_t xh = *(const uint32_t*)(Rhi + idx);
                uint32_t xl = *(const uint32_t*)(Rlo + idx);
                float r0v = __half2float(__ushort_as_half((unsigned short)(xh & 0xffff)))
                          + __half2float(__ushort_as_half((unsigned short)(xl & 0xffff)));
                float r1v = __half2float(__ushort_as_half((unsigned short)(xh >> 16)))
                          + __half2float(__ushort_as_half((unsigned short)(xl >> 16)));
                tr[(col_l)     * 68 + row_l + h * 8] = acc[mf][nf][2*h]     + r0v;
                tr[(col_l + 1) * 68 + row_l + h * 8] = acc[mf][nf][2*h + 1] + r1v;
            }
        }
    __syncthreads();
#pragma unroll
    for (int it = 0; it < 16; it++) {
        int col = (tid >> 4) + it * 16;
        int t4  = (tid & 15) * 4;
        float4 v = *(float4*)&tr[col * 68 + t4];
        *(float4*)(out + ((size_t)z * NC + col) * NT + m0 + t4) = v;
    }
}

// ============================================================
__global__ void __launch_bounds__(256) ln_kernel(
    const float* __restrict__ x, const float* __restrict__ gamma,
    const float* __restrict__ beta, h16* __restrict__ xnhi, h16* __restrict__ xnlo)
{
    __shared__ float sx[32][NC + 1];
    __shared__ float psum[8][33], psq[8][33];
    __shared__ float smu[32], srs[32];
    int b = blockIdx.y, n0 = blockIdx.x * 32;
    const float* xb = x + (size_t)b * NC * NT;

    for (int i = threadIdx.x; i < NC * 32; i += 256) {
        int c = i >> 5, t = i & 31;
        sx[t][c] = xb[(size_t)c * NT + n0 + t];
    }
    __syncthreads();
    int t = threadIdx.x & 31, g = threadIdx.x >> 5;
    float s0 = 0.f, s1 = 0.f;
#pragma unroll
    for (int j = 0; j < 32; j++) { float v = sx[t][g * 32 + j]; s0 += v; s1 += v * v; }
    psum[g][t] = s0; psq[g][t] = s1;
    __syncthreads();
    if (threadIdx.x < 32) {
        float a = 0.f, bb = 0.f;
#pragma unroll
        for (int j = 0; j < 8; j++) { a += psum[j][threadIdx.x]; bb += psq[j][threadIdx.x]; }
        float mu = a * (1.0f / NC);
        smu[threadIdx.x] = mu;
        srs[threadIdx.x] = rsqrtf(bb * (1.0f / NC) - mu * mu + 1e-5f);
    }
    __syncthreads();
    size_t base = ((size_t)b * NT + n0) * NC;
    for (int i = threadIdx.x; i < NC * 32; i += 256) {
        int tok = i >> 8, c = i & 255;
        float r = (sx[tok][c] - smu[tok]) * srs[tok] * gamma[c] + beta[c];
        float h = __half2float(__float2half_rn(r));
        xnhi[base + (size_t)tok * NC + c] = __float2half_rn(r);
        xnlo[base + (size_t)tok * NC + c] = __float2half_rn(r - h);
    }
}

__global__ void prep_kernel(
    const float* __restrict__ Wq, const float* __restrict__ Wk, const float* __restrict__ Wv,
    h16* qh, h16* kh, h16* vh)
{
    int n = blockIdx.x, k = threadIdx.x;
    size_t src = (size_t)k * NC + n, dst = (size_t)n * NC + k;
    qh[dst] = __float2half_rn(Wq[src]);
    kh[dst] = __float2half_rn(Wk[src]);
    vh[dst] = __float2half_rn(Wv[src]);
}

// mix: attn = a1*softmax + a2*relu^2, fp16 in/out
__global__ void __launch_bounds__(256) mix_kernel(
    const float* __restrict__ w1, const float* __restrict__ w2,
    const h16* __restrict__ S, h16* __restrict__ ahi)
{
    size_t ro = ((size_t)blockIdx.y * NT + blockIdx.x) * NT;
    const uint2* row2 = (const uint2*)(S + ro);
    int tid = threadIdx.x;
    __shared__ float sred[8];

    float v[16];
    float mx = -1e30f;
#pragma unroll
    for (int g = 0; g < 4; g++) {
        uint2 u = row2[g * 256 + tid];
        v[g*4+0] = __half2float(__ushort_as_half((unsigned short)(u.x & 0xffff)));
        v[g*4+1] = __half2float(__ushort_as_half((unsigned short)(u.x >> 16)));
        v[g*4+2] = __half2float(__ushort_as_half((unsigned short)(u.y & 0xffff)));
        v[g*4+3] = __half2float(__ushort_as_half((unsigned short)(u.y >> 16)));
    }
#pragma unroll
    for (int i = 0; i < 16; i++) mx = fmaxf(mx, v[i]);
#pragma unroll
    for (int o = 16; o; o >>= 1) mx = fmaxf(mx, __shfl_xor_sync(0xffffffffu, mx, o));
    if ((tid & 31) == 0) sred[tid >> 5] = mx;
    __syncthreads();
    mx = sred[0];
#pragma unroll
    for (int i = 1; i < 8; i++) mx = fmaxf(mx, sred[i]);
    __syncthreads();

    float e[16];
    float sum = 0.f;
#pragma unroll
    for (int i = 0; i < 16; i++) { e[i] = __expf(v[i] - mx); sum += e[i]; }
#pragma unroll
    for (int o = 16; o; o >>= 1) sum += __shfl_xor_sync(0xffffffffu, sum, o);
    if ((tid & 31) == 0) sred[tid >> 5] = sum;
    __syncthreads();
    sum = 0.f;
#pragma unroll
    for (int i = 0; i < 8; i++) sum += sred[i];

    float e1 = __expf(w1[0]), e2 = __expf(w2[0]);
    float a1 = e1 / (e1 + e2), a2 = e2 / (e1 + e2);
    float inv = a1 / sum;

    uint2* oh = (uint2*)(ahi + ro);
#pragma unroll
    for (int g = 0; g < 4; g++) {
        float p[4];
#pragma unroll
        for (int j = 0; j < 4; j++) {
            float r = fmaxf(v[g*4+j], 0.f);
            p[j] = e[g*4+j] * inv + a2 * r * r;
        }
        oh[g * 256 + tid] = make_uint2(pack2h(p[0], p[1]), pack2h(p[2], p[3]));
    }
}

// ============================================================
extern "C" void kernel_launch(void* const* d_in, const int* in_sizes, int n_in,
                              void* d_out, int out_size)
{
    const float* x     = (const float*)d_in[0];
    const float* gamma = (const float*)d_in[1];
    const float* beta  = (const float*)d_in[2];
    const float* Wq    = (const float*)d_in[3];
    const float* Wk    = (const float*)d_in[4];
    const float* Wv    = (const float*)d_in[5];
    const float* w1    = (const float*)d_in[6];
    const float* w2    = (const float*)d_in[7];
    float* out = (float*)d_out;

    h16 *xnhi, *xnlo, *qhi, *khi, *vThi, *wqhi, *wkhi, *wvhi, *ahi, *s16;
    cudaGetSymbolAddress((void**)&xnhi, g_xnhi); cudaGetSymbolAddress((void**)&xnlo, g_xnlo);
    cudaGetSymbolAddress((void**)&qhi,  g_qhi);
    cudaGetSymbolAddress((void**)&khi,  g_khi);
    cudaGetSymbolAddress((void**)&vThi, g_vThi);
    cudaGetSymbolAddress((void**)&wqhi, g_wqhi);
    cudaGetSymbolAddress((void**)&wkhi, g_wkhi);
    cudaGetSymbolAddress((void**)&wvhi, g_wvhi);
    cudaGetSymbolAddress((void**)&ahi,  g_ahi);  cudaGetSymbolAddress((void**)&s16,  g_s16);

    cudaFuncSetAttribute((const void*)mma_gemm,   cudaFuncAttributeMaxDynamicSharedMemorySize, 98304);
    cudaFuncSetAttribute((const void*)mma_o_gemm, cudaFuncAttributeMaxDynamicSharedMemorySize, 98304);

    // 1) LayerNorm -> xn pair
    ln_kernel<<<dim3(NT / 32, NB), 256>>>(x, gamma, beta, xnhi, xnlo);
    // 2) weight transpose (fp16 hi only)
    prep_kernel<<<NC, NC>>>(Wq, Wk, Wv, wqhi, wkhi, wvhi);
    // 3-5) Q, K, V^T projections (pure fp16)
    mma_gemm<<<dim3(2, 128, 1), 256, 98304>>>(
        xnhi, NC, 0, wqhi, NC, 0, qhi, NC, 0, NC);
    mma_gemm<<<dim3(2, 128, 1), 256, 98304>>>(
        xnhi, NC, 0, wkhi, NC, 0, khi, NC, 0, NC);
    mma_gemm<<<dim3(128, 2, 1), 256, 98304>>>(
        wvhi, NC, 0, xnhi, NC, 0, vThi, (long)NB * NT, 0, NC);
    // 6) S = Q K^T (fp16 out)  <- ncu 6th launch
    mma_gemm<<<dim3(32, 32, NB), 256, 98304>>>(
        qhi, NC, (long)NT * NC, khi, NC, (long)NT * NC,
        s16, NT, (long)NT * NT, NC);
    // 7) attn mix (fp16 in/out)
    mix_kernel<<<dim3(NT, NB), 256>>>(w1, w2, s16, ahi);
    // 8) O = attn @ V + residual + transpose -> out[b,c,n]  (BN=256)
    mma_o_gemm<<<dim3(1, 64, NB), 256, 98304>>>(ahi, vThi, xnhi, xnlo, out);
}